// round 1
// baseline (speedup 1.0000x reference)
#include <cuda_runtime.h>
#include <math.h>

#define NN 65536
#define NE 524288
#define EX (NE + NN)
#define DD 128

// ---------------- scratch (device globals: allocation-free) ----------------
__device__ float g_h[(size_t)NN * DD];      // 32MB: h = x @ W
__device__ float g_x[(size_t)NN * DD];      // 32MB: layer activations
__device__ float g_as[NN];                  // h . att_src
__device__ float g_ad[NN];                  // h . att_dst
__device__ float g_ess[3][EX];              // per-(layer,slot) edge score, CSR order
__device__ float g_essum[3][NN];            // sum of edge scores per dst (for self-loop fill)
__device__ int   g_srcs[EX];                // CSR src array
__device__ int   g_rowptr[NN + 1];
__device__ int   g_wslot[NN];
__device__ int   g_cnt[NN];
__device__ float g_ve[3][32];               // We[l] @ att_edge[l]

__device__ __forceinline__ float gelu_f(float x) {
    return 0.5f * x * (1.0f + erff(x * 0.7071067811865476f));
}

// ---------------- preprocessing ----------------
__global__ void k_init() {
    int i = blockIdx.x * blockDim.x + threadIdx.x;
    if (i < NN) {
        g_cnt[i] = 0;
        g_essum[0][i] = 0.f; g_essum[1][i] = 0.f; g_essum[2][i] = 0.f;
    }
}

__global__ void k_ve(const float* __restrict__ We, const float* __restrict__ ae) {
    int t = threadIdx.x;
    if (t < 96) {
        int l = t / 32, k = t % 32;
        const float* w = We + l * 32 * DD + k * DD;
        const float* a = ae + l * DD;
        float s = 0.f;
        #pragma unroll 8
        for (int d = 0; d < DD; d++) s += w[d] * a[d];
        g_ve[l][k] = s;
    }
}

__global__ void k_hist(const int* __restrict__ ei) {
    int e = blockIdx.x * blockDim.x + threadIdx.x;
    if (e < NE) atomicAdd(&g_cnt[ei[NE + e]], 1);
}

__global__ void k_scan() {  // single block, 1024 threads; 64 nodes/thread
    __shared__ int ps[1024];
    int tid = threadIdx.x;
    int base = tid * 64;
    int s = 0;
    for (int i = 0; i < 64; i++) s += g_cnt[base + i] + 1;  // +1 self loop
    ps[tid] = s;
    __syncthreads();
    for (int off = 1; off < 1024; off <<= 1) {
        int v = (tid >= off) ? ps[tid - off] : 0;
        __syncthreads();
        ps[tid] += v;
        __syncthreads();
    }
    int run = (tid ? ps[tid - 1] : 0);
    for (int i = 0; i < 64; i++) {
        int n = base + i;
        g_rowptr[n] = run;
        g_wslot[n] = run;
        run += g_cnt[n] + 1;
    }
    if (tid == 0) g_rowptr[NN] = EX;
}

__global__ void k_scatter(const int* __restrict__ ei, const float* __restrict__ ea) {
    __shared__ float sve[96];
    if (threadIdx.x < 96) sve[threadIdx.x] = ((const float*)g_ve)[threadIdx.x];
    __syncthreads();
    int e = blockIdx.x * blockDim.x + threadIdx.x;
    if (e >= NE) return;
    int s = ei[e];
    int d = ei[NE + e];
    const float4* a4 = (const float4*)(ea + (size_t)e * 32);
    float dot0 = 0.f, dot1 = 0.f, dot2 = 0.f;
    #pragma unroll
    for (int q = 0; q < 8; q++) {
        float4 v = a4[q];
        const float* v0 = sve + 0 * 32 + q * 4;
        const float* v1 = sve + 1 * 32 + q * 4;
        const float* v2 = sve + 2 * 32 + q * 4;
        dot0 += v.x * v0[0] + v.y * v0[1] + v.z * v0[2] + v.w * v0[3];
        dot1 += v.x * v1[0] + v.y * v1[1] + v.z * v1[2] + v.w * v1[3];
        dot2 += v.x * v2[0] + v.y * v2[1] + v.z * v2[2] + v.w * v2[3];
    }
    int p = atomicAdd(&g_wslot[d], 1);
    g_srcs[p] = s;
    g_ess[0][p] = dot0; g_ess[1][p] = dot1; g_ess[2][p] = dot2;
    atomicAdd(&g_essum[0][d], dot0);
    atomicAdd(&g_essum[1][d], dot1);
    atomicAdd(&g_essum[2][d], dot2);
}

__global__ void k_selfloop() {
    int n = blockIdx.x * blockDim.x + threadIdx.x;
    if (n >= NN) return;
    int pos = g_rowptr[n + 1] - 1;
    g_srcs[pos] = n;
    float cf = fmaxf((float)g_cnt[n], 1.0f);
    g_ess[0][pos] = g_essum[0][n] / cf;
    g_ess[1][pos] = g_essum[1][n] / cf;
    g_ess[2][pos] = g_essum[2][n] / cf;
}

// ---------------- GEMM: g_h = A(65536x128) @ B(128x128), fp32 SIMT ----------------
__global__ void __launch_bounds__(256) k_gemm(const float* __restrict__ Ain,
                                              const float* __restrict__ B) {
    __shared__ float As[2][16][128];
    __shared__ float Bs[2][16][128];
    const float* A = Ain ? Ain : g_x;
    const int tid = threadIdx.x;
    const int tx = tid & 15, ty = tid >> 4;
    const int row0 = blockIdx.x * 128;

    const int a_r = tid >> 2;           // 0..63
    const int a_c = (tid & 3) << 2;     // 0,4,8,12
    const int b_r = tid >> 5;           // 0..7
    const int b_c = (tid & 31) << 2;    // 0..124

    float acc[8][8];
    #pragma unroll
    for (int i = 0; i < 8; i++)
        #pragma unroll
        for (int j = 0; j < 8; j++) acc[i][j] = 0.f;

    float4 ra0, ra1, rb0, rb1;

    // prologue: tile 0
    {
        const float* Ab = A + (size_t)row0 * DD;
        ra0 = *(const float4*)(Ab + (size_t)a_r * DD + a_c);
        ra1 = *(const float4*)(Ab + (size_t)(a_r + 64) * DD + a_c);
        const float* Bb = B;
        rb0 = *(const float4*)(Bb + b_r * DD + b_c);
        rb1 = *(const float4*)(Bb + (b_r + 8) * DD + b_c);
        As[0][a_c + 0][a_r] = ra0.x; As[0][a_c + 1][a_r] = ra0.y;
        As[0][a_c + 2][a_r] = ra0.z; As[0][a_c + 3][a_r] = ra0.w;
        As[0][a_c + 0][a_r + 64] = ra1.x; As[0][a_c + 1][a_r + 64] = ra1.y;
        As[0][a_c + 2][a_r + 64] = ra1.z; As[0][a_c + 3][a_r + 64] = ra1.w;
        *(float4*)&Bs[0][b_r][b_c] = rb0;
        *(float4*)&Bs[0][b_r + 8][b_c] = rb1;
    }
    __syncthreads();

    int buf = 0;
    #pragma unroll
    for (int kt = 0; kt < 8; kt++) {
        if (kt < 7) {
            const float* Ab = A + (size_t)row0 * DD + (kt + 1) * 16;
            ra0 = *(const float4*)(Ab + (size_t)a_r * DD + a_c);
            ra1 = *(const float4*)(Ab + (size_t)(a_r + 64) * DD + a_c);
            const float* Bb = B + (kt + 1) * 16 * DD;
            rb0 = *(const float4*)(Bb + b_r * DD + b_c);
            rb1 = *(const float4*)(Bb + (b_r + 8) * DD + b_c);
        }
        #pragma unroll
        for (int k = 0; k < 16; k++) {
            float a[8], b[8];
            #pragma unroll
            for (int i = 0; i < 8; i++) a[i] = As[buf][k][ty * 8 + i];
            #pragma unroll
            for (int j = 0; j < 8; j++) b[j] = Bs[buf][k][tx * 8 + j];
            #pragma unroll
            for (int i = 0; i < 8; i++)
                #pragma unroll
                for (int j = 0; j < 8; j++) acc[i][j] = fmaf(a[i], b[j], acc[i][j]);
        }
        if (kt < 7) {
            int nb = buf ^ 1;
            As[nb][a_c + 0][a_r] = ra0.x; As[nb][a_c + 1][a_r] = ra0.y;
            As[nb][a_c + 2][a_r] = ra0.z; As[nb][a_c + 3][a_r] = ra0.w;
            As[nb][a_c + 0][a_r + 64] = ra1.x; As[nb][a_c + 1][a_r + 64] = ra1.y;
            As[nb][a_c + 2][a_r + 64] = ra1.z; As[nb][a_c + 3][a_r + 64] = ra1.w;
            *(float4*)&Bs[nb][b_r][b_c] = rb0;
            *(float4*)&Bs[nb][b_r + 8][b_c] = rb1;
            __syncthreads();
            buf = nb;
        }
    }

    #pragma unroll
    for (int i = 0; i < 8; i++) {
        float4 v0 = make_float4(acc[i][0], acc[i][1], acc[i][2], acc[i][3]);
        float4 v1 = make_float4(acc[i][4], acc[i][5], acc[i][6], acc[i][7]);
        float* Cr = g_h + (size_t)(row0 + ty * 8 + i) * DD + tx * 8;
        *(float4*)Cr = v0;
        *(float4*)(Cr + 4) = v1;
    }
}

// ---------------- row dots: as[i] = h_i . att_src, ad[i] = h_i . att_dst ----------------
__global__ void k_rowdots(const float* __restrict__ a_s, const float* __restrict__ a_d) {
    int w = (blockIdx.x * blockDim.x + threadIdx.x) >> 5;
    int lane = threadIdx.x & 31;
    if (w >= NN) return;
    float4 v = ((const float4*)g_h)[(size_t)w * 32 + lane];
    float4 s4 = ((const float4*)a_s)[lane];
    float4 d4 = ((const float4*)a_d)[lane];
    float ss = v.x * s4.x + v.y * s4.y + v.z * s4.z + v.w * s4.w;
    float dd = v.x * d4.x + v.y * d4.y + v.z * d4.z + v.w * d4.w;
    #pragma unroll
    for (int o = 16; o; o >>= 1) {
        ss += __shfl_xor_sync(0xffffffffu, ss, o);
        dd += __shfl_xor_sync(0xffffffffu, dd, o);
    }
    if (lane == 0) { g_as[w] = ss; g_ad[w] = dd; }
}

// ---------------- fused attention + aggregate + bias + GELU (warp per dst node) ----------------
__global__ void __launch_bounds__(256) k_agg(int l, const float* __restrict__ bias_l,
                                             float* __restrict__ outp) {
    int d = (blockIdx.x * blockDim.x + threadIdx.x) >> 5;
    int lane = threadIdx.x & 31;
    if (d >= NN) return;
    float* out = outp ? outp : g_x;

    int beg = g_rowptr[d];
    int end = g_rowptr[d + 1];
    float add = g_ad[d];
    const float* ess = g_ess[l];

    // pass A: segment max of leaky-relu'd logits
    float m = -3.0e38f;
    for (int j = beg + lane; j < end; j += 32) {
        int s = g_srcs[j];
        float al = g_as[s] + add + ess[j];
        al = al > 0.f ? al : 0.2f * al;
        m = fmaxf(m, al);
    }
    #pragma unroll
    for (int o = 16; o; o >>= 1) m = fmaxf(m, __shfl_xor_sync(0xffffffffu, m, o));

    // pass B: unnormalized weighted sum of h[src], plus denominator
    float den = 0.f;
    float4 acc = make_float4(0.f, 0.f, 0.f, 0.f);
    const float4* h4 = (const float4*)g_h;

    for (int base = beg; base < end; base += 32) {
        int j = base + lane;
        float ex = 0.f;
        int s = 0;
        if (j < end) {
            s = g_srcs[j];
            float al = g_as[s] + add + ess[j];
            al = al > 0.f ? al : 0.2f * al;
            ex = __expf(al - m);
        }
        den += ex;
        int cnt = end - base;
        if (cnt > 32) cnt = 32;
        for (int t = 0; t < cnt; t++) {
            float ext = __shfl_sync(0xffffffffu, ex, t);
            int st = __shfl_sync(0xffffffffu, s, t);
            float4 v = h4[(size_t)st * 32 + lane];
            acc.x = fmaf(ext, v.x, acc.x);
            acc.y = fmaf(ext, v.y, acc.y);
            acc.z = fmaf(ext, v.z, acc.z);
            acc.w = fmaf(ext, v.w, acc.w);
        }
    }
    #pragma unroll
    for (int o = 16; o; o >>= 1) den += __shfl_xor_sync(0xffffffffu, den, o);
    float r = 1.0f / den;

    float4 b4 = ((const float4*)bias_l)[lane];
    float4 o4;
    o4.x = gelu_f(fmaf(acc.x, r, b4.x));
    o4.y = gelu_f(fmaf(acc.y, r, b4.y));
    o4.z = gelu_f(fmaf(acc.z, r, b4.z));
    o4.w = gelu_f(fmaf(acc.w, r, b4.w));
    ((float4*)out)[(size_t)d * 32 + lane] = o4;
}

// ---------------- launch ----------------
extern "C" void kernel_launch(void* const* d_in, const int* in_sizes, int n_in,
                              void* d_out, int out_size) {
    const float* x    = (const float*)d_in[0];
    const int*   ei   = (const int*)d_in[1];
    const float* ea   = (const float*)d_in[2];
    const float* Ws   = (const float*)d_in[3];
    const float* a_s  = (const float*)d_in[4];
    const float* a_d  = (const float*)d_in[5];
    const float* We   = (const float*)d_in[6];
    const float* ae   = (const float*)d_in[7];
    const float* bias = (const float*)d_in[8];
    float* out = (float*)d_out;

    k_init<<<NN / 256, 256>>>();
    k_ve<<<1, 128>>>(We, ae);
    k_hist<<<NE / 256, 256>>>(ei);
    k_scan<<<1, 1024>>>();
    k_scatter<<<NE / 256, 256>>>(ei, ea);
    k_selfloop<<<NN / 256, 256>>>();

    for (int l = 0; l < 3; l++) {
        const float* xin = (l == 0) ? x : nullptr;        // nullptr -> g_x inside
        k_gemm<<<NN / 128, 256>>>(xin, Ws + (size_t)l * DD * DD);
        k_rowdots<<<NN / 8, 256>>>(a_s + l * DD, a_d + l * DD);
        float* outl = (l == 2) ? out : nullptr;           // nullptr -> g_x inside
        k_agg<<<NN / 8, 256>>>(l, bias + l * DD, outl);
    }
}

// round 2
// speedup vs baseline: 1.3766x; 1.3766x over previous
#include <cuda_runtime.h>
#include <math.h>

#define NN 65536
#define NE 524288
#define EX (NE + NN)
#define DD 128

// ---------------- scratch (device globals: allocation-free) ----------------
__device__ float g_h[(size_t)NN * DD];      // 32MB: h = x @ W
__device__ float g_x[(size_t)NN * DD];      // 32MB: layer activations
__device__ float g_as[NN];                  // h . att_src
__device__ float g_ad[NN];                  // h . att_dst
__device__ float g_ess[3][EX];              // per-(layer,slot) edge score, CSR order
__device__ float g_essum[3][NN];            // sum of edge scores per dst (for self-loop fill)
__device__ int   g_srcs[EX];                // CSR src array
__device__ int   g_rowptr[NN + 1];
__device__ int   g_wslot[NN];
__device__ int   g_cnt[NN];
__device__ int   g_bsum[256];               // per-block sums for parallel scan
__device__ float g_ve[3][32];               // We[l] @ att_edge[l]

__device__ __forceinline__ float gelu_f(float x) {
    return 0.5f * x * (1.0f + erff(x * 0.7071067811865476f));
}

// ---------------- preprocessing ----------------
__global__ void k_init() {
    int i = blockIdx.x * blockDim.x + threadIdx.x;
    if (i < NN) {
        g_cnt[i] = 0;
        g_essum[0][i] = 0.f; g_essum[1][i] = 0.f; g_essum[2][i] = 0.f;
    }
}

__global__ void k_ve(const float* __restrict__ We, const float* __restrict__ ae) {
    int t = threadIdx.x;
    if (t < 96) {
        int l = t / 32, k = t % 32;
        const float* w = We + l * 32 * DD + k * DD;
        const float* a = ae + l * DD;
        float s = 0.f;
        #pragma unroll 8
        for (int d = 0; d < DD; d++) s += w[d] * a[d];
        g_ve[l][k] = s;
    }
}

__global__ void k_hist(const int* __restrict__ ei) {
    int e = blockIdx.x * blockDim.x + threadIdx.x;
    if (e < NE) atomicAdd(&g_cnt[ei[NE + e]], 1);
}

// ---- parallel scan over (cnt[n] + 1), 65536 elements = 256 blocks x 256 ----
__global__ void k_bsum() {
    int b = blockIdx.x, t = threadIdx.x;
    int v = g_cnt[b * 256 + t] + 1;
    #pragma unroll
    for (int o = 16; o; o >>= 1) v += __shfl_xor_sync(0xffffffffu, v, o);
    __shared__ int ws[8];
    if ((t & 31) == 0) ws[t >> 5] = v;
    __syncthreads();
    if (t < 8) {
        int s = ws[t];
        #pragma unroll
        for (int o = 4; o; o >>= 1) s += __shfl_xor_sync(0xffu, s, o);
        if (t == 0) g_bsum[b] = s;
    }
}

__global__ void k_bscan() {  // single tiny block: exclusive scan of 256 block sums
    int t = threadIdx.x;
    int lane = t & 31, w = t >> 5;
    int v = g_bsum[t];
    int x = v;
    #pragma unroll
    for (int o = 1; o < 32; o <<= 1) {
        int y = __shfl_up_sync(0xffffffffu, x, o);
        if (lane >= o) x += y;
    }
    __shared__ int ws[8];
    if (lane == 31) ws[w] = x;
    __syncthreads();
    if (t < 8) {
        int s = ws[t];
        #pragma unroll
        for (int o = 1; o < 8; o <<= 1) {
            int y = __shfl_up_sync(0xffu, s, o);
            if (t >= o) s += y;
        }
        ws[t] = s;
    }
    __syncthreads();
    int incl = x + (w ? ws[w - 1] : 0);
    g_bsum[t] = incl - v;            // exclusive block offset
    if (t == 255) g_rowptr[NN] = EX;
}

__global__ void k_rowptr() {
    int b = blockIdx.x, t = threadIdx.x;
    int n = b * 256 + t;
    int lane = t & 31, w = t >> 5;
    int v = g_cnt[n] + 1;
    int x = v;
    #pragma unroll
    for (int o = 1; o < 32; o <<= 1) {
        int y = __shfl_up_sync(0xffffffffu, x, o);
        if (lane >= o) x += y;
    }
    __shared__ int ws[8];
    if (lane == 31) ws[w] = x;
    __syncthreads();
    if (t < 8) {
        int s = ws[t];
        #pragma unroll
        for (int o = 1; o < 8; o <<= 1) {
            int y = __shfl_up_sync(0xffu, s, o);
            if (t >= o) s += y;
        }
        ws[t] = s;
    }
    __syncthreads();
    int excl = x - v + (w ? ws[w - 1] : 0) + g_bsum[b];
    g_rowptr[n] = excl;
    g_wslot[n] = excl;
}

__global__ void k_scatter(const int* __restrict__ ei, const float* __restrict__ ea) {
    __shared__ float sve[96];
    if (threadIdx.x < 96) sve[threadIdx.x] = ((const float*)g_ve)[threadIdx.x];
    __syncthreads();
    int e = blockIdx.x * blockDim.x + threadIdx.x;
    if (e >= NE) return;
    int s = ei[e];
    int d = ei[NE + e];
    const float4* a4 = (const float4*)(ea + (size_t)e * 32);
    float dot0 = 0.f, dot1 = 0.f, dot2 = 0.f;
    #pragma unroll
    for (int q = 0; q < 8; q++) {
        float4 v = a4[q];
        const float* v0 = sve + 0 * 32 + q * 4;
        const float* v1 = sve + 1 * 32 + q * 4;
        const float* v2 = sve + 2 * 32 + q * 4;
        dot0 += v.x * v0[0] + v.y * v0[1] + v.z * v0[2] + v.w * v0[3];
        dot1 += v.x * v1[0] + v.y * v1[1] + v.z * v1[2] + v.w * v1[3];
        dot2 += v.x * v2[0] + v.y * v2[1] + v.z * v2[2] + v.w * v2[3];
    }
    int p = atomicAdd(&g_wslot[d], 1);
    g_srcs[p] = s;
    g_ess[0][p] = dot0; g_ess[1][p] = dot1; g_ess[2][p] = dot2;
    atomicAdd(&g_essum[0][d], dot0);
    atomicAdd(&g_essum[1][d], dot1);
    atomicAdd(&g_essum[2][d], dot2);
}

__global__ void k_selfloop() {
    int n = blockIdx.x * blockDim.x + threadIdx.x;
    if (n >= NN) return;
    int pos = g_rowptr[n + 1] - 1;
    g_srcs[pos] = n;
    float cf = fmaxf((float)g_cnt[n], 1.0f);
    g_ess[0][pos] = g_essum[0][n] / cf;
    g_ess[1][pos] = g_essum[1][n] / cf;
    g_ess[2][pos] = g_essum[2][n] / cf;
}

// ---------------- GEMM: g_h = A(65536x128) @ B(128x128), fp32 SIMT ----------------
__global__ void __launch_bounds__(256) k_gemm(const float* __restrict__ Ain,
                                              const float* __restrict__ B) {
    __shared__ float As[2][16][128];
    __shared__ float Bs[2][16][128];
    const float* A = Ain ? Ain : g_x;
    const int tid = threadIdx.x;
    const int tx = tid & 15, ty = tid >> 4;
    const int row0 = blockIdx.x * 128;

    const int a_r = tid >> 2;           // 0..63
    const int a_c = (tid & 3) << 2;     // 0,4,8,12
    const int b_r = tid >> 5;           // 0..7
    const int b_c = (tid & 31) << 2;    // 0..124

    float acc[8][8];
    #pragma unroll
    for (int i = 0; i < 8; i++)
        #pragma unroll
        for (int j = 0; j < 8; j++) acc[i][j] = 0.f;

    float4 ra0, ra1, rb0, rb1;

    {
        const float* Ab = A + (size_t)row0 * DD;
        ra0 = *(const float4*)(Ab + (size_t)a_r * DD + a_c);
        ra1 = *(const float4*)(Ab + (size_t)(a_r + 64) * DD + a_c);
        const float* Bb = B;
        rb0 = *(const float4*)(Bb + b_r * DD + b_c);
        rb1 = *(const float4*)(Bb + (b_r + 8) * DD + b_c);
        As[0][a_c + 0][a_r] = ra0.x; As[0][a_c + 1][a_r] = ra0.y;
        As[0][a_c + 2][a_r] = ra0.z; As[0][a_c + 3][a_r] = ra0.w;
        As[0][a_c + 0][a_r + 64] = ra1.x; As[0][a_c + 1][a_r + 64] = ra1.y;
        As[0][a_c + 2][a_r + 64] = ra1.z; As[0][a_c + 3][a_r + 64] = ra1.w;
        *(float4*)&Bs[0][b_r][b_c] = rb0;
        *(float4*)&Bs[0][b_r + 8][b_c] = rb1;
    }
    __syncthreads();

    int buf = 0;
    #pragma unroll
    for (int kt = 0; kt < 8; kt++) {
        if (kt < 7) {
            const float* Ab = A + (size_t)row0 * DD + (kt + 1) * 16;
            ra0 = *(const float4*)(Ab + (size_t)a_r * DD + a_c);
            ra1 = *(const float4*)(Ab + (size_t)(a_r + 64) * DD + a_c);
            const float* Bb = B + (kt + 1) * 16 * DD;
            rb0 = *(const float4*)(Bb + b_r * DD + b_c);
            rb1 = *(const float4*)(Bb + (b_r + 8) * DD + b_c);
        }
        #pragma unroll
        for (int k = 0; k < 16; k++) {
            float a[8], b[8];
            #pragma unroll
            for (int i = 0; i < 8; i++) a[i] = As[buf][k][ty * 8 + i];
            #pragma unroll
            for (int j = 0; j < 8; j++) b[j] = Bs[buf][k][tx * 8 + j];
            #pragma unroll
            for (int i = 0; i < 8; i++)
                #pragma unroll
                for (int j = 0; j < 8; j++) acc[i][j] = fmaf(a[i], b[j], acc[i][j]);
        }
        if (kt < 7) {
            int nb = buf ^ 1;
            As[nb][a_c + 0][a_r] = ra0.x; As[nb][a_c + 1][a_r] = ra0.y;
            As[nb][a_c + 2][a_r] = ra0.z; As[nb][a_c + 3][a_r] = ra0.w;
            As[nb][a_c + 0][a_r + 64] = ra1.x; As[nb][a_c + 1][a_r + 64] = ra1.y;
            As[nb][a_c + 2][a_r + 64] = ra1.z; As[nb][a_c + 3][a_r + 64] = ra1.w;
            *(float4*)&Bs[nb][b_r][b_c] = rb0;
            *(float4*)&Bs[nb][b_r + 8][b_c] = rb1;
            __syncthreads();
            buf = nb;
        }
    }

    #pragma unroll
    for (int i = 0; i < 8; i++) {
        float4 v0 = make_float4(acc[i][0], acc[i][1], acc[i][2], acc[i][3]);
        float4 v1 = make_float4(acc[i][4], acc[i][5], acc[i][6], acc[i][7]);
        float* Cr = g_h + (size_t)(row0 + ty * 8 + i) * DD + tx * 8;
        *(float4*)Cr = v0;
        *(float4*)(Cr + 4) = v1;
    }
}

// ---------------- row dots ----------------
__global__ void k_rowdots(const float* __restrict__ a_s, const float* __restrict__ a_d) {
    int w = (blockIdx.x * blockDim.x + threadIdx.x) >> 5;
    int lane = threadIdx.x & 31;
    if (w >= NN) return;
    float4 v = ((const float4*)g_h)[(size_t)w * 32 + lane];
    float4 s4 = ((const float4*)a_s)[lane];
    float4 d4 = ((const float4*)a_d)[lane];
    float ss = v.x * s4.x + v.y * s4.y + v.z * s4.z + v.w * s4.w;
    float dd = v.x * d4.x + v.y * d4.y + v.z * d4.z + v.w * d4.w;
    #pragma unroll
    for (int o = 16; o; o >>= 1) {
        ss += __shfl_xor_sync(0xffffffffu, ss, o);
        dd += __shfl_xor_sync(0xffffffffu, dd, o);
    }
    if (lane == 0) { g_as[w] = ss; g_ad[w] = dd; }
}

// ---------------- fused attention + aggregate + bias + GELU ----------------
__global__ void __launch_bounds__(256) k_agg(int l, const float* __restrict__ bias_l,
                                             float* __restrict__ outp) {
    int d = (blockIdx.x * blockDim.x + threadIdx.x) >> 5;
    int lane = threadIdx.x & 31;
    if (d >= NN) return;
    float* out = outp ? outp : g_x;

    int beg = g_rowptr[d];
    int end = g_rowptr[d + 1];
    float add = g_ad[d];
    const float* ess = g_ess[l];

    float m = -3.0e38f;
    for (int j = beg + lane; j < end; j += 32) {
        int s = g_srcs[j];
        float al = g_as[s] + add + ess[j];
        al = al > 0.f ? al : 0.2f * al;
        m = fmaxf(m, al);
    }
    #pragma unroll
    for (int o = 16; o; o >>= 1) m = fmaxf(m, __shfl_xor_sync(0xffffffffu, m, o));

    float den = 0.f;
    float4 acc = make_float4(0.f, 0.f, 0.f, 0.f);
    const float4* h4 = (const float4*)g_h;

    for (int base = beg; base < end; base += 32) {
        int j = base + lane;
        float ex = 0.f;
        int s = 0;
        if (j < end) {
            s = g_srcs[j];
            float al = g_as[s] + add + ess[j];
            al = al > 0.f ? al : 0.2f * al;
            ex = __expf(al - m);
        }
        den += ex;
        int cnt = end - base;
        if (cnt > 32) cnt = 32;
        for (int t = 0; t < cnt; t++) {
            float ext = __shfl_sync(0xffffffffu, ex, t);
            int st = __shfl_sync(0xffffffffu, s, t);
            float4 v = h4[(size_t)st * 32 + lane];
            acc.x = fmaf(ext, v.x, acc.x);
            acc.y = fmaf(ext, v.y, acc.y);
            acc.z = fmaf(ext, v.z, acc.z);
            acc.w = fmaf(ext, v.w, acc.w);
        }
    }
    #pragma unroll
    for (int o = 16; o; o >>= 1) den += __shfl_xor_sync(0xffffffffu, den, o);
    float r = 1.0f / den;

    float4 b4 = ((const float4*)bias_l)[lane];
    float4 o4;
    o4.x = gelu_f(fmaf(acc.x, r, b4.x));
    o4.y = gelu_f(fmaf(acc.y, r, b4.y));
    o4.z = gelu_f(fmaf(acc.z, r, b4.z));
    o4.w = gelu_f(fmaf(acc.w, r, b4.w));
    ((float4*)out)[(size_t)d * 32 + lane] = o4;
}

// ---------------- launch ----------------
extern "C" void kernel_launch(void* const* d_in, const int* in_sizes, int n_in,
                              void* d_out, int out_size) {
    const float* x    = (const float*)d_in[0];
    const int*   ei   = (const int*)d_in[1];
    const float* ea   = (const float*)d_in[2];
    const float* Ws   = (const float*)d_in[3];
    const float* a_s  = (const float*)d_in[4];
    const float* a_d  = (const float*)d_in[5];
    const float* We   = (const float*)d_in[6];
    const float* ae   = (const float*)d_in[7];
    const float* bias = (const float*)d_in[8];
    float* out = (float*)d_out;

    k_init<<<NN / 256, 256>>>();
    k_ve<<<1, 128>>>(We, ae);
    k_hist<<<NE / 256, 256>>>(ei);
    k_bsum<<<256, 256>>>();
    k_bscan<<<1, 256>>>();
    k_rowptr<<<256, 256>>>();
    k_scatter<<<NE / 256, 256>>>(ei, ea);
    k_selfloop<<<NN / 256, 256>>>();

    for (int l = 0; l < 3; l++) {
        const float* xin = (l == 0) ? x : nullptr;        // nullptr -> g_x inside
        k_gemm<<<NN / 128, 256>>>(xin, Ws + (size_t)l * DD * DD);
        k_rowdots<<<NN / 8, 256>>>(a_s + l * DD, a_d + l * DD);
        float* outl = (l == 2) ? out : nullptr;           // nullptr -> g_x inside
        k_agg<<<NN / 8, 256>>>(l, bias + l * DD, outl);
    }
}

// round 3
// speedup vs baseline: 1.5155x; 1.1009x over previous
#include <cuda_runtime.h>
#include <cuda_bf16.h>
#include <math.h>

#define NN 65536
#define NE 524288
#define EX (NE + NN)
#define DD 128
#define PA 132   // padded A row (f32 elems)
#define PB 136   // padded Bt row (bf16 elems)

// ---------------- scratch (device globals: allocation-free) ----------------
__device__ float g_h[(size_t)NN * DD];
__device__ float g_x[(size_t)NN * DD];
__device__ float g_as[NN];
__device__ float g_ad[NN];
__device__ float g_ess[3][EX];
__device__ float g_essum[3][NN];
__device__ int   g_srcs[EX];
__device__ int   g_rowptr[NN + 1];
__device__ int   g_wslot[NN];
__device__ int   g_cnt[NN];
__device__ int   g_bsum[256];
__device__ float g_ve[3][32];

__device__ __forceinline__ float gelu_f(float x) {
    return 0.5f * x * (1.0f + erff(x * 0.7071067811865476f));
}

// ---------------- preprocessing ----------------
__global__ void k_init() {
    int i = blockIdx.x * blockDim.x + threadIdx.x;
    if (i < NN) {
        g_cnt[i] = 0;
        g_essum[0][i] = 0.f; g_essum[1][i] = 0.f; g_essum[2][i] = 0.f;
    }
}

__global__ void k_ve(const float* __restrict__ We, const float* __restrict__ ae) {
    int t = threadIdx.x;
    if (t < 96) {
        int l = t / 32, k = t % 32;
        const float* w = We + l * 32 * DD + k * DD;
        const float* a = ae + l * DD;
        float s = 0.f;
        #pragma unroll 8
        for (int d = 0; d < DD; d++) s += w[d] * a[d];
        g_ve[l][k] = s;
    }
}

__global__ void k_hist(const int* __restrict__ ei) {
    int e = blockIdx.x * blockDim.x + threadIdx.x;
    if (e < NE) atomicAdd(&g_cnt[ei[NE + e]], 1);
}

__global__ void k_bsum() {
    int b = blockIdx.x, t = threadIdx.x;
    int v = g_cnt[b * 256 + t] + 1;
    #pragma unroll
    for (int o = 16; o; o >>= 1) v += __shfl_xor_sync(0xffffffffu, v, o);
    __shared__ int ws[8];
    if ((t & 31) == 0) ws[t >> 5] = v;
    __syncthreads();
    if (t < 8) {
        int s = ws[t];
        #pragma unroll
        for (int o = 4; o; o >>= 1) s += __shfl_xor_sync(0xffu, s, o);
        if (t == 0) g_bsum[b] = s;
    }
}

__global__ void k_bscan() {
    int t = threadIdx.x;
    int lane = t & 31, w = t >> 5;
    int v = g_bsum[t];
    int x = v;
    #pragma unroll
    for (int o = 1; o < 32; o <<= 1) {
        int y = __shfl_up_sync(0xffffffffu, x, o);
        if (lane >= o) x += y;
    }
    __shared__ int ws[8];
    if (lane == 31) ws[w] = x;
    __syncthreads();
    if (t < 8) {
        int s = ws[t];
        #pragma unroll
        for (int o = 1; o < 8; o <<= 1) {
            int y = __shfl_up_sync(0xffu, s, o);
            if (t >= o) s += y;
        }
        ws[t] = s;
    }
    __syncthreads();
    int incl = x + (w ? ws[w - 1] : 0);
    g_bsum[t] = incl - v;
    if (t == 255) g_rowptr[NN] = EX;
}

__global__ void k_rowptr() {
    int b = blockIdx.x, t = threadIdx.x;
    int n = b * 256 + t;
    int lane = t & 31, w = t >> 5;
    int v = g_cnt[n] + 1;
    int x = v;
    #pragma unroll
    for (int o = 1; o < 32; o <<= 1) {
        int y = __shfl_up_sync(0xffffffffu, x, o);
        if (lane >= o) x += y;
    }
    __shared__ int ws[8];
    if (lane == 31) ws[w] = x;
    __syncthreads();
    if (t < 8) {
        int s = ws[t];
        #pragma unroll
        for (int o = 1; o < 8; o <<= 1) {
            int y = __shfl_up_sync(0xffu, s, o);
            if (t >= o) s += y;
        }
        ws[t] = s;
    }
    __syncthreads();
    int excl = x - v + (w ? ws[w - 1] : 0) + g_bsum[b];
    g_rowptr[n] = excl;
    g_wslot[n] = excl;
}

__global__ void k_scatter(const int* __restrict__ ei, const float* __restrict__ ea) {
    __shared__ float sve[96];
    if (threadIdx.x < 96) sve[threadIdx.x] = ((const float*)g_ve)[threadIdx.x];
    __syncthreads();
    int e = blockIdx.x * blockDim.x + threadIdx.x;
    if (e >= NE) return;
    int s = ei[e];
    int d = ei[NE + e];
    const float4* a4 = (const float4*)(ea + (size_t)e * 32);
    float dot0 = 0.f, dot1 = 0.f, dot2 = 0.f;
    #pragma unroll
    for (int q = 0; q < 8; q++) {
        float4 v = a4[q];
        const float* v0 = sve + 0 * 32 + q * 4;
        const float* v1 = sve + 1 * 32 + q * 4;
        const float* v2 = sve + 2 * 32 + q * 4;
        dot0 += v.x * v0[0] + v.y * v0[1] + v.z * v0[2] + v.w * v0[3];
        dot1 += v.x * v1[0] + v.y * v1[1] + v.z * v1[2] + v.w * v1[3];
        dot2 += v.x * v2[0] + v.y * v2[1] + v.z * v2[2] + v.w * v2[3];
    }
    int p = atomicAdd(&g_wslot[d], 1);
    g_srcs[p] = s;
    g_ess[0][p] = dot0; g_ess[1][p] = dot1; g_ess[2][p] = dot2;
    atomicAdd(&g_essum[0][d], dot0);
    atomicAdd(&g_essum[1][d], dot1);
    atomicAdd(&g_essum[2][d], dot2);
}

__global__ void k_selfloop() {
    int n = blockIdx.x * blockDim.x + threadIdx.x;
    if (n >= NN) return;
    int pos = g_rowptr[n + 1] - 1;
    g_srcs[pos] = n;
    float cf = fmaxf((float)g_cnt[n], 1.0f);
    g_ess[0][pos] = g_essum[0][n] / cf;
    g_ess[1][pos] = g_essum[1][n] / cf;
    g_ess[2][pos] = g_essum[2][n] / cf;
}

// ---------------- tensor-core GEMM: g_h = A(65536x128) @ W(128x128) ----------------
// split-bf16 3-product fp32 emulation on mma.sync.m16n8k16
__device__ __forceinline__ void mma16816(float* c, const unsigned* a, const unsigned* b) {
    asm volatile(
        "mma.sync.aligned.m16n8k16.row.col.f32.bf16.bf16.f32 "
        "{%0,%1,%2,%3},{%4,%5,%6,%7},{%8,%9},{%0,%1,%2,%3};\n"
        : "+f"(c[0]), "+f"(c[1]), "+f"(c[2]), "+f"(c[3])
        : "r"(a[0]), "r"(a[1]), "r"(a[2]), "r"(a[3]), "r"(b[0]), "r"(b[1]));
}

__device__ __forceinline__ void split2(float2 v, unsigned& hi, unsigned& lo) {
    __nv_bfloat16 hx = __float2bfloat16_rn(v.x);
    __nv_bfloat16 hy = __float2bfloat16_rn(v.y);
    float lx = v.x - __bfloat162float(hx);
    float ly = v.y - __bfloat162float(hy);
    __nv_bfloat162 h2; h2.x = hx; h2.y = hy;
    __nv_bfloat162 l2 = __floats2bfloat162_rn(lx, ly);
    hi = *(unsigned*)&h2;
    lo = *(unsigned*)&l2;
}

extern __shared__ char smem_raw[];

__global__ void __launch_bounds__(256) k_gemm_tc(const float* __restrict__ Ain,
                                                 const float* __restrict__ B) {
    const float* A = Ain ? Ain : g_x;
    float* sA = (float*)smem_raw;                                    // [128][PA] f32
    __nv_bfloat16* sBh = (__nv_bfloat16*)(smem_raw + 128 * PA * 4);  // [128][PB] n-major
    __nv_bfloat16* sBl = sBh + 128 * PB;

    int tid = threadIdx.x;
    int row0 = blockIdx.x * 128;

    // stage A tile (fp32, padded)
    {
        const float4* A4 = (const float4*)(A + (size_t)row0 * DD);
        #pragma unroll
        for (int it = 0; it < 16; it++) {
            int idx = it * 256 + tid;
            int r = idx >> 5;
            int c = (idx & 31) << 2;
            float4 v = A4[idx];
            float* dst = sA + r * PA + c;
            dst[0] = v.x; dst[1] = v.y; dst[2] = v.z; dst[3] = v.w;
        }
    }
    // stage W transposed -> bf16 hi/lo, n-major
    {
        const float4* B4 = (const float4*)B;
        #pragma unroll
        for (int it = 0; it < 16; it++) {
            int idx = it * 256 + tid;
            int k = idx >> 5;
            int n = (idx & 31) << 2;
            float4 v = B4[idx];
            float vv[4] = {v.x, v.y, v.z, v.w};
            #pragma unroll
            for (int q = 0; q < 4; q++) {
                __nv_bfloat16 h = __float2bfloat16_rn(vv[q]);
                float lo = vv[q] - __bfloat162float(h);
                sBh[(n + q) * PB + k] = h;
                sBl[(n + q) * PB + k] = __float2bfloat16_rn(lo);
            }
        }
    }
    __syncthreads();

    int wid = tid >> 5, lane = tid & 31;
    int g = lane >> 2, t = lane & 3;
    int wm = wid >> 2, wn = wid & 3;        // 2 x 4 warp grid, 64x32 per warp
    int mbase = wm * 64, nbase = wn * 32;

    float acc[4][4][4];
    #pragma unroll
    for (int i = 0; i < 4; i++)
        #pragma unroll
        for (int j = 0; j < 4; j++)
            #pragma unroll
            for (int q = 0; q < 4; q++) acc[i][j][q] = 0.f;

    #pragma unroll
    for (int kk = 0; kk < 8; kk++) {
        int k0 = kk * 16;
        unsigned Ah[4][4], Al[4][4];
        #pragma unroll
        for (int i = 0; i < 4; i++) {
            int r = mbase + i * 16 + g;
            const float* p0 = sA + r * PA + k0 + 2 * t;
            const float* p1 = sA + (r + 8) * PA + k0 + 2 * t;
            split2(*(const float2*)(p0),     Ah[i][0], Al[i][0]);
            split2(*(const float2*)(p1),     Ah[i][1], Al[i][1]);
            split2(*(const float2*)(p0 + 8), Ah[i][2], Al[i][2]);
            split2(*(const float2*)(p1 + 8), Ah[i][3], Al[i][3]);
        }
        unsigned Bh[4][2], Bl[4][2];
        #pragma unroll
        for (int j = 0; j < 4; j++) {
            int n = nbase + j * 8 + g;
            const __nv_bfloat16* ph = sBh + n * PB + k0 + 2 * t;
            const __nv_bfloat16* pl = sBl + n * PB + k0 + 2 * t;
            Bh[j][0] = *(const unsigned*)(ph);
            Bh[j][1] = *(const unsigned*)(ph + 8);
            Bl[j][0] = *(const unsigned*)(pl);
            Bl[j][1] = *(const unsigned*)(pl + 8);
        }
        #pragma unroll
        for (int i = 0; i < 4; i++)
            #pragma unroll
            for (int j = 0; j < 4; j++) {
                mma16816(acc[i][j], Ah[i], Bh[j]);
                mma16816(acc[i][j], Al[i], Bh[j]);
                mma16816(acc[i][j], Ah[i], Bl[j]);
            }
    }

    #pragma unroll
    for (int i = 0; i < 4; i++) {
        int r = row0 + mbase + i * 16 + g;
        #pragma unroll
        for (int j = 0; j < 4; j++) {
            int c = nbase + j * 8 + 2 * t;
            *(float2*)(g_h + (size_t)r * DD + c) = make_float2(acc[i][j][0], acc[i][j][1]);
            *(float2*)(g_h + (size_t)(r + 8) * DD + c) = make_float2(acc[i][j][2], acc[i][j][3]);
        }
    }
}

// ---------------- row dots ----------------
__global__ void k_rowdots(const float* __restrict__ a_s, const float* __restrict__ a_d) {
    int w = (blockIdx.x * blockDim.x + threadIdx.x) >> 5;
    int lane = threadIdx.x & 31;
    if (w >= NN) return;
    float4 v = ((const float4*)g_h)[(size_t)w * 32 + lane];
    float4 s4 = ((const float4*)a_s)[lane];
    float4 d4 = ((const float4*)a_d)[lane];
    float ss = v.x * s4.x + v.y * s4.y + v.z * s4.z + v.w * s4.w;
    float dd = v.x * d4.x + v.y * d4.y + v.z * d4.z + v.w * d4.w;
    #pragma unroll
    for (int o = 16; o; o >>= 1) {
        ss += __shfl_xor_sync(0xffffffffu, ss, o);
        dd += __shfl_xor_sync(0xffffffffu, dd, o);
    }
    if (lane == 0) { g_as[w] = ss; g_ad[w] = dd; }
}

// ---------------- fused attention + aggregate + bias + GELU ----------------
__global__ void __launch_bounds__(256) k_agg(int l, const float* __restrict__ bias_l,
                                             float* __restrict__ outp) {
    int d = (blockIdx.x * blockDim.x + threadIdx.x) >> 5;
    int lane = threadIdx.x & 31;
    if (d >= NN) return;
    float* out = outp ? outp : g_x;

    int beg = g_rowptr[d];
    int end = g_rowptr[d + 1];
    float add = g_ad[d];
    const float* ess = g_ess[l];

    float m = -3.0e38f;
    for (int j = beg + lane; j < end; j += 32) {
        int s = g_srcs[j];
        float al = g_as[s] + add + ess[j];
        al = al > 0.f ? al : 0.2f * al;
        m = fmaxf(m, al);
    }
    #pragma unroll
    for (int o = 16; o; o >>= 1) m = fmaxf(m, __shfl_xor_sync(0xffffffffu, m, o));

    float den = 0.f;
    float4 acc = make_float4(0.f, 0.f, 0.f, 0.f);
    const float4* h4 = (const float4*)g_h;

    for (int base = beg; base < end; base += 32) {
        int j = base + lane;
        float ex = 0.f;
        int s = 0;
        if (j < end) {
            s = g_srcs[j];
            float al = g_as[s] + add + ess[j];
            al = al > 0.f ? al : 0.2f * al;
            ex = __expf(al - m);
        }
        den += ex;
        int cnt = end - base;
        if (cnt > 32) cnt = 32;
        for (int t = 0; t < cnt; t++) {
            float ext = __shfl_sync(0xffffffffu, ex, t);
            int st = __shfl_sync(0xffffffffu, s, t);
            float4 v = h4[(size_t)st * 32 + lane];
            acc.x = fmaf(ext, v.x, acc.x);
            acc.y = fmaf(ext, v.y, acc.y);
            acc.z = fmaf(ext, v.z, acc.z);
            acc.w = fmaf(ext, v.w, acc.w);
        }
    }
    #pragma unroll
    for (int o = 16; o; o >>= 1) den += __shfl_xor_sync(0xffffffffu, den, o);
    float r = 1.0f / den;

    float4 b4 = ((const float4*)bias_l)[lane];
    float4 o4;
    o4.x = gelu_f(fmaf(acc.x, r, b4.x));
    o4.y = gelu_f(fmaf(acc.y, r, b4.y));
    o4.z = gelu_f(fmaf(acc.z, r, b4.z));
    o4.w = gelu_f(fmaf(acc.w, r, b4.w));
    ((float4*)out)[(size_t)d * 32 + lane] = o4;
}

// ---------------- launch ----------------
extern "C" void kernel_launch(void* const* d_in, const int* in_sizes, int n_in,
                              void* d_out, int out_size) {
    const float* x    = (const float*)d_in[0];
    const int*   ei   = (const int*)d_in[1];
    const float* ea   = (const float*)d_in[2];
    const float* Ws   = (const float*)d_in[3];
    const float* a_s  = (const float*)d_in[4];
    const float* a_d  = (const float*)d_in[5];
    const float* We   = (const float*)d_in[6];
    const float* ae   = (const float*)d_in[7];
    const float* bias = (const float*)d_in[8];
    float* out = (float*)d_out;

    const int SMEM_SZ = 128 * PA * 4 + 2 * 128 * PB * 2;  // 137216 B
    cudaFuncSetAttribute(k_gemm_tc, cudaFuncAttributeMaxDynamicSharedMemorySize, SMEM_SZ);

    k_init<<<NN / 256, 256>>>();
    k_ve<<<1, 128>>>(We, ae);
    k_hist<<<NE / 256, 256>>>(ei);
    k_bsum<<<256, 256>>>();
    k_bscan<<<1, 256>>>();
    k_rowptr<<<256, 256>>>();
    k_scatter<<<NE / 256, 256>>>(ei, ea);
    k_selfloop<<<NN / 256, 256>>>();

    for (int l = 0; l < 3; l++) {
        const float* xin = (l == 0) ? x : nullptr;
        k_gemm_tc<<<NN / 128, 256, SMEM_SZ>>>(xin, Ws + (size_t)l * DD * DD);
        k_rowdots<<<NN / 8, 256>>>(a_s + l * DD, a_d + l * DD);
        float* outl = (l == 2) ? out : nullptr;
        k_agg<<<NN / 8, 256>>>(l, bias + l * DD, outl);
    }
}

// round 4
// speedup vs baseline: 2.0562x; 1.3568x over previous
#include <cuda_runtime.h>
#include <cuda_bf16.h>
#include <math.h>

#define NN 65536
#define NE 524288
#define EX (NE + NN)
#define DD 128
#define PK 136   // padded k-dim (bf16 elems); 272B rows => ldmatrix conflict-free

// ---------------- scratch (device globals: allocation-free) ----------------
__device__ float g_h[(size_t)NN * DD];
__device__ float g_x[(size_t)NN * DD];
__device__ float g_as[NN];
__device__ float g_ad[NN];
__device__ float g_ess[3][EX];
__device__ float g_essum[3][NN];
__device__ int   g_srcs[EX];
__device__ int   g_rowptr[NN + 1];
__device__ int   g_wslot[NN];
__device__ int   g_cnt[NN];
__device__ int   g_bsum[256];
__device__ float g_ve[3][32];
__device__ __nv_bfloat16 g_wh[3][DD * DD];   // W^T split hi (n-major)
__device__ __nv_bfloat16 g_wl[3][DD * DD];   // W^T split lo (n-major)

__device__ __forceinline__ float gelu_f(float x) {
    return 0.5f * x * (1.0f + erff(x * 0.7071067811865476f));
}

// ---------------- preprocessing ----------------
__global__ void k_init() {
    int i = blockIdx.x * blockDim.x + threadIdx.x;
    if (i < NN) {
        g_cnt[i] = 0;
        g_essum[0][i] = 0.f; g_essum[1][i] = 0.f; g_essum[2][i] = 0.f;
    }
}

__global__ void k_ve(const float* __restrict__ We, const float* __restrict__ ae) {
    int t = threadIdx.x;
    if (t < 96) {
        int l = t / 32, k = t % 32;
        const float* w = We + l * 32 * DD + k * DD;
        const float* a = ae + l * DD;
        float s = 0.f;
        #pragma unroll 8
        for (int d = 0; d < DD; d++) s += w[d] * a[d];
        g_ve[l][k] = s;
    }
}

// split W into bf16 hi/lo, transposed to n-major, once for all layers
__global__ void k_wsplit(const float* __restrict__ Ws) {
    int idx = blockIdx.x * blockDim.x + threadIdx.x;   // 3*128*128
    int l = idx >> 14;
    int rem = idx & 16383;
    int k = rem >> 7, n = rem & 127;
    float v = Ws[idx];
    __nv_bfloat16 h = __float2bfloat16_rn(v);
    float lo = v - __bfloat162float(h);
    g_wh[l][n * DD + k] = h;
    g_wl[l][n * DD + k] = __float2bfloat16_rn(lo);
}

__global__ void k_hist(const int* __restrict__ ei) {
    int e = blockIdx.x * blockDim.x + threadIdx.x;
    if (e < NE) atomicAdd(&g_cnt[ei[NE + e]], 1);
}

__global__ void k_bsum() {
    int b = blockIdx.x, t = threadIdx.x;
    int v = g_cnt[b * 256 + t] + 1;
    #pragma unroll
    for (int o = 16; o; o >>= 1) v += __shfl_xor_sync(0xffffffffu, v, o);
    __shared__ int ws[8];
    if ((t & 31) == 0) ws[t >> 5] = v;
    __syncthreads();
    if (t < 8) {
        int s = ws[t];
        #pragma unroll
        for (int o = 4; o; o >>= 1) s += __shfl_xor_sync(0xffu, s, o);
        if (t == 0) g_bsum[b] = s;
    }
}

__global__ void k_bscan() {
    int t = threadIdx.x;
    int lane = t & 31, w = t >> 5;
    int v = g_bsum[t];
    int x = v;
    #pragma unroll
    for (int o = 1; o < 32; o <<= 1) {
        int y = __shfl_up_sync(0xffffffffu, x, o);
        if (lane >= o) x += y;
    }
    __shared__ int ws[8];
    if (lane == 31) ws[w] = x;
    __syncthreads();
    if (t < 8) {
        int s = ws[t];
        #pragma unroll
        for (int o = 1; o < 8; o <<= 1) {
            int y = __shfl_up_sync(0xffu, s, o);
            if (t >= o) s += y;
        }
        ws[t] = s;
    }
    __syncthreads();
    int incl = x + (w ? ws[w - 1] : 0);
    g_bsum[t] = incl - v;
    if (t == 255) g_rowptr[NN] = EX;
}

__global__ void k_rowptr() {
    int b = blockIdx.x, t = threadIdx.x;
    int n = b * 256 + t;
    int lane = t & 31, w = t >> 5;
    int v = g_cnt[n] + 1;
    int x = v;
    #pragma unroll
    for (int o = 1; o < 32; o <<= 1) {
        int y = __shfl_up_sync(0xffffffffu, x, o);
        if (lane >= o) x += y;
    }
    __shared__ int ws[8];
    if (lane == 31) ws[w] = x;
    __syncthreads();
    if (t < 8) {
        int s = ws[t];
        #pragma unroll
        for (int o = 1; o < 8; o <<= 1) {
            int y = __shfl_up_sync(0xffu, s, o);
            if (t >= o) s += y;
        }
        ws[t] = s;
    }
    __syncthreads();
    int excl = x - v + (w ? ws[w - 1] : 0) + g_bsum[b];
    g_rowptr[n] = excl;
    g_wslot[n] = excl;
}

__global__ void k_scatter(const int* __restrict__ ei, const float* __restrict__ ea) {
    __shared__ float sve[96];
    if (threadIdx.x < 96) sve[threadIdx.x] = ((const float*)g_ve)[threadIdx.x];
    __syncthreads();
    int e = blockIdx.x * blockDim.x + threadIdx.x;
    if (e >= NE) return;
    int s = ei[e];
    int d = ei[NE + e];
    const float4* a4 = (const float4*)(ea + (size_t)e * 32);
    float dot0 = 0.f, dot1 = 0.f, dot2 = 0.f;
    #pragma unroll
    for (int q = 0; q < 8; q++) {
        float4 v = a4[q];
        const float* v0 = sve + 0 * 32 + q * 4;
        const float* v1 = sve + 1 * 32 + q * 4;
        const float* v2 = sve + 2 * 32 + q * 4;
        dot0 += v.x * v0[0] + v.y * v0[1] + v.z * v0[2] + v.w * v0[3];
        dot1 += v.x * v1[0] + v.y * v1[1] + v.z * v1[2] + v.w * v1[3];
        dot2 += v.x * v2[0] + v.y * v2[1] + v.z * v2[2] + v.w * v2[3];
    }
    int p = atomicAdd(&g_wslot[d], 1);
    g_srcs[p] = s;
    g_ess[0][p] = dot0; g_ess[1][p] = dot1; g_ess[2][p] = dot2;
    atomicAdd(&g_essum[0][d], dot0);
    atomicAdd(&g_essum[1][d], dot1);
    atomicAdd(&g_essum[2][d], dot2);
}

__global__ void k_selfloop() {
    int n = blockIdx.x * blockDim.x + threadIdx.x;
    if (n >= NN) return;
    int pos = g_rowptr[n + 1] - 1;
    g_srcs[pos] = n;
    float cf = fmaxf((float)g_cnt[n], 1.0f);
    g_ess[0][pos] = g_essum[0][n] / cf;
    g_ess[1][pos] = g_essum[1][n] / cf;
    g_ess[2][pos] = g_essum[2][n] / cf;
}

// ---------------- tensor-core GEMM ----------------
__device__ __forceinline__ void mma16816(float* c, const unsigned* a, const unsigned* b) {
    asm volatile(
        "mma.sync.aligned.m16n8k16.row.col.f32.bf16.bf16.f32 "
        "{%0,%1,%2,%3},{%4,%5,%6,%7},{%8,%9},{%0,%1,%2,%3};\n"
        : "+f"(c[0]), "+f"(c[1]), "+f"(c[2]), "+f"(c[3])
        : "r"(a[0]), "r"(a[1]), "r"(a[2]), "r"(a[3]), "r"(b[0]), "r"(b[1]));
}

__device__ __forceinline__ void ldm_x4(unsigned* r, unsigned addr) {
    asm volatile("ldmatrix.sync.aligned.m8n8.x4.shared.b16 {%0,%1,%2,%3},[%4];"
                 : "=r"(r[0]), "=r"(r[1]), "=r"(r[2]), "=r"(r[3]) : "r"(addr));
}

__device__ __forceinline__ void ldm_x2(unsigned* r, unsigned addr) {
    asm volatile("ldmatrix.sync.aligned.m8n8.x2.shared.b16 {%0,%1},[%2];"
                 : "=r"(r[0]), "=r"(r[1]) : "r"(addr));
}

extern __shared__ char smem_raw[];

__global__ void __launch_bounds__(256) k_gemm_tc(const float* __restrict__ Ain, int l) {
    const float* A = Ain ? Ain : g_x;
    __nv_bfloat16* sAh = (__nv_bfloat16*)smem_raw;      // [128][PK]
    __nv_bfloat16* sAl = sAh + 128 * PK;
    __nv_bfloat16* sBh = sAl + 128 * PK;                // n-major [128][PK]
    __nv_bfloat16* sBl = sBh + 128 * PK;

    int tid = threadIdx.x;
    int row0 = blockIdx.x * 128;

    // stage A: fp32 -> bf16 hi/lo split, conflict-free 8B stores
    {
        const float4* A4 = (const float4*)(A + (size_t)row0 * DD);
        #pragma unroll
        for (int it = 0; it < 16; it++) {
            int idx = it * 256 + tid;
            int r = idx >> 5;
            int c = (idx & 31) << 2;
            float4 v = A4[idx];
            __nv_bfloat16 h0 = __float2bfloat16_rn(v.x), h1 = __float2bfloat16_rn(v.y);
            __nv_bfloat16 h2 = __float2bfloat16_rn(v.z), h3 = __float2bfloat16_rn(v.w);
            __nv_bfloat162 ha, hb, la, lb;
            ha.x = h0; ha.y = h1; hb.x = h2; hb.y = h3;
            la = __floats2bfloat162_rn(v.x - __bfloat162float(h0), v.y - __bfloat162float(h1));
            lb = __floats2bfloat162_rn(v.z - __bfloat162float(h2), v.w - __bfloat162float(h3));
            unsigned* dh = (unsigned*)(sAh + r * PK + c);
            unsigned* dl = (unsigned*)(sAl + r * PK + c);
            dh[0] = *(unsigned*)&ha; dh[1] = *(unsigned*)&hb;
            dl[0] = *(unsigned*)&la; dl[1] = *(unsigned*)&lb;
        }
    }
    // stage W (pre-split, n-major): pure uint4 copy, conflict-free
    {
        const uint4* wh4 = (const uint4*)g_wh[l];
        const uint4* wl4 = (const uint4*)g_wl[l];
        #pragma unroll
        for (int it = 0; it < 8; it++) {
            int idx = it * 256 + tid;
            int n = idx >> 4;
            int kc = idx & 15;
            ((uint4*)(sBh + n * PK))[kc] = wh4[idx];
            ((uint4*)(sBl + n * PK))[kc] = wl4[idx];
        }
    }
    __syncthreads();

    int wid = tid >> 5, lane = tid & 31;
    int g = lane >> 2, tq = lane & 3;
    int wm = wid >> 2, wn = wid & 3;        // 2 x 4 warp grid: 64x32 per warp
    int mbase = wm * 64, nbase = wn * 32;

    // ldmatrix base addresses (bytes)
    unsigned baseAh, baseAl, baseBh, baseBl;
    {
        int aoff = ((mbase + (lane & 15)) * PK + ((lane >> 4) << 3)) * 2;
        baseAh = (unsigned)__cvta_generic_to_shared(sAh) + aoff;
        baseAl = (unsigned)__cvta_generic_to_shared(sAl) + aoff;
        int boff = ((nbase + (lane & 7)) * PK + (((lane >> 3) & 1) << 3)) * 2;
        baseBh = (unsigned)__cvta_generic_to_shared(sBh) + boff;
        baseBl = (unsigned)__cvta_generic_to_shared(sBl) + boff;
    }

    float acc[4][4][4];
    #pragma unroll
    for (int i = 0; i < 4; i++)
        #pragma unroll
        for (int j = 0; j < 4; j++)
            #pragma unroll
            for (int q = 0; q < 4; q++) acc[i][j][q] = 0.f;

    #pragma unroll
    for (int kk = 0; kk < 8; kk++) {
        unsigned kb = kk * 32;   // 16 bf16 = 32 bytes
        unsigned Ah[4][4], Al[4][4], Bh[4][2], Bl[4][2];
        #pragma unroll
        for (int i = 0; i < 4; i++) {
            unsigned off = (unsigned)(i * 16 * PK * 2) + kb;
            ldm_x4(Ah[i], baseAh + off);
            ldm_x4(Al[i], baseAl + off);
        }
        #pragma unroll
        for (int j = 0; j < 4; j++) {
            unsigned off = (unsigned)(j * 8 * PK * 2) + kb;
            ldm_x2(Bh[j], baseBh + off);
            ldm_x2(Bl[j], baseBl + off);
        }
        #pragma unroll
        for (int i = 0; i < 4; i++)
            #pragma unroll
            for (int j = 0; j < 4; j++) {
                mma16816(acc[i][j], Ah[i], Bh[j]);
                mma16816(acc[i][j], Al[i], Bh[j]);
                mma16816(acc[i][j], Ah[i], Bl[j]);
            }
    }

    #pragma unroll
    for (int i = 0; i < 4; i++) {
        int r = row0 + mbase + i * 16 + g;
        #pragma unroll
        for (int j = 0; j < 4; j++) {
            int c = nbase + j * 8 + 2 * tq;
            *(float2*)(g_h + (size_t)r * DD + c) = make_float2(acc[i][j][0], acc[i][j][1]);
            *(float2*)(g_h + (size_t)(r + 8) * DD + c) = make_float2(acc[i][j][2], acc[i][j][3]);
        }
    }
}

// ---------------- row dots ----------------
__global__ void k_rowdots(const float* __restrict__ a_s, const float* __restrict__ a_d) {
    int w = (blockIdx.x * blockDim.x + threadIdx.x) >> 5;
    int lane = threadIdx.x & 31;
    if (w >= NN) return;
    float4 v = ((const float4*)g_h)[(size_t)w * 32 + lane];
    float4 s4 = ((const float4*)a_s)[lane];
    float4 d4 = ((const float4*)a_d)[lane];
    float ss = v.x * s4.x + v.y * s4.y + v.z * s4.z + v.w * s4.w;
    float dd = v.x * d4.x + v.y * d4.y + v.z * d4.z + v.w * d4.w;
    #pragma unroll
    for (int o = 16; o; o >>= 1) {
        ss += __shfl_xor_sync(0xffffffffu, ss, o);
        dd += __shfl_xor_sync(0xffffffffu, dd, o);
    }
    if (lane == 0) { g_as[w] = ss; g_ad[w] = dd; }
}

// ---------------- fused attention + aggregate + bias + GELU ----------------
__global__ void __launch_bounds__(256) k_agg(int l, const float* __restrict__ bias_l,
                                             float* __restrict__ outp) {
    int d = (blockIdx.x * blockDim.x + threadIdx.x) >> 5;
    int lane = threadIdx.x & 31;
    if (d >= NN) return;
    float* out = outp ? outp : g_x;

    int beg = g_rowptr[d];
    int end = g_rowptr[d + 1];
    float add = g_ad[d];
    const float* ess = g_ess[l];

    float m = -3.0e38f;
    for (int j = beg + lane; j < end; j += 32) {
        int s = g_srcs[j];
        float al = g_as[s] + add + ess[j];
        al = al > 0.f ? al : 0.2f * al;
        m = fmaxf(m, al);
    }
    #pragma unroll
    for (int o = 16; o; o >>= 1) m = fmaxf(m, __shfl_xor_sync(0xffffffffu, m, o));

    float den = 0.f;
    float4 acc = make_float4(0.f, 0.f, 0.f, 0.f);
    const float4* h4 = (const float4*)g_h;

    for (int base = beg; base < end; base += 32) {
        int j = base + lane;
        float ex = 0.f;
        int s = 0;
        if (j < end) {
            s = g_srcs[j];
            float al = g_as[s] + add + ess[j];
            al = al > 0.f ? al : 0.2f * al;
            ex = __expf(al - m);
        }
        den += ex;
        int cnt = end - base;
        if (cnt > 32) cnt = 32;
        for (int t = 0; t < cnt; t++) {
            float ext = __shfl_sync(0xffffffffu, ex, t);
            int st = __shfl_sync(0xffffffffu, s, t);
            float4 v = h4[(size_t)st * 32 + lane];
            acc.x = fmaf(ext, v.x, acc.x);
            acc.y = fmaf(ext, v.y, acc.y);
            acc.z = fmaf(ext, v.z, acc.z);
            acc.w = fmaf(ext, v.w, acc.w);
        }
    }
    #pragma unroll
    for (int o = 16; o; o >>= 1) den += __shfl_xor_sync(0xffffffffu, den, o);
    float r = 1.0f / den;

    float4 b4 = ((const float4*)bias_l)[lane];
    float4 o4;
    o4.x = gelu_f(fmaf(acc.x, r, b4.x));
    o4.y = gelu_f(fmaf(acc.y, r, b4.y));
    o4.z = gelu_f(fmaf(acc.z, r, b4.z));
    o4.w = gelu_f(fmaf(acc.w, r, b4.w));
    ((float4*)out)[(size_t)d * 32 + lane] = o4;
}

// ---------------- launch ----------------
extern "C" void kernel_launch(void* const* d_in, const int* in_sizes, int n_in,
                              void* d_out, int out_size) {
    const float* x    = (const float*)d_in[0];
    const int*   ei   = (const int*)d_in[1];
    const float* ea   = (const float*)d_in[2];
    const float* Ws   = (const float*)d_in[3];
    const float* a_s  = (const float*)d_in[4];
    const float* a_d  = (const float*)d_in[5];
    const float* We   = (const float*)d_in[6];
    const float* ae   = (const float*)d_in[7];
    const float* bias = (const float*)d_in[8];
    float* out = (float*)d_out;

    const int SMEM_SZ = 4 * 128 * PK * 2;  // 139264 B
    cudaFuncSetAttribute(k_gemm_tc, cudaFuncAttributeMaxDynamicSharedMemorySize, SMEM_SZ);

    k_init<<<NN / 256, 256>>>();
    k_ve<<<1, 128>>>(We, ae);
    k_wsplit<<<192, 256>>>(Ws);
    k_hist<<<NE / 256, 256>>>(ei);
    k_bsum<<<256, 256>>>();
    k_bscan<<<1, 256>>>();
    k_rowptr<<<256, 256>>>();
    k_scatter<<<NE / 256, 256>>>(ei, ea);
    k_selfloop<<<NN / 256, 256>>>();

    for (int l = 0; l < 3; l++) {
        const float* xin = (l == 0) ? x : nullptr;
        k_gemm_tc<<<NN / 128, 256, SMEM_SZ>>>(xin, l);
        k_rowdots<<<NN / 8, 256>>>(a_s + l * DD, a_d + l * DD);
        float* outl = (l == 2) ? out : nullptr;
        k_agg<<<NN / 8, 256>>>(l, bias + l * DD, outl);
    }
}

// round 5
// speedup vs baseline: 2.1322x; 1.0370x over previous
#include <cuda_runtime.h>
#include <cuda_bf16.h>
#include <math.h>

#define NN 65536
#define NE 524288
#define EX (NE + NN)
#define DD 128
#define PK 136   // padded k-dim (bf16 elems); 272B rows => ldmatrix conflict-free

// ---------------- scratch (device globals: allocation-free) ----------------
__device__ float g_h[(size_t)NN * DD];
__device__ float g_x[(size_t)NN * DD];
__device__ float g_as[NN];
__device__ float g_ad[NN];
__device__ float g_ess[3][EX];
__device__ float g_essum[3][NN];
__device__ int   g_srcs[EX];
__device__ int   g_rowptr[NN + 1];
__device__ int   g_wslot[NN];
__device__ int   g_cnt[NN];
__device__ int   g_bsum[256];
__device__ float g_ve[3][32];
__device__ __nv_bfloat16 g_wh[3][DD * DD];   // W^T split hi (n-major)
__device__ __nv_bfloat16 g_wl[3][DD * DD];   // W^T split lo (n-major)

__device__ __forceinline__ float gelu_f(float x) {
    return 0.5f * x * (1.0f + erff(x * 0.7071067811865476f));
}

// ---------------- preprocessing ----------------
__global__ void k_init() {
    int i = blockIdx.x * blockDim.x + threadIdx.x;
    if (i < NN) {
        g_cnt[i] = 0;
        g_essum[0][i] = 0.f; g_essum[1][i] = 0.f; g_essum[2][i] = 0.f;
    }
}

// blocks 0..191: split W into bf16 hi/lo (transposed, n-major).
// block 192: compute ve[l] = We[l] @ att_edge[l].
__global__ void k_wsplit(const float* __restrict__ Ws,
                         const float* __restrict__ We, const float* __restrict__ ae) {
    if (blockIdx.x == 192) {
        int t = threadIdx.x;
        if (t < 96) {
            int l = t / 32, k = t % 32;
            const float* w = We + l * 32 * DD + k * DD;
            const float* a = ae + l * DD;
            float s = 0.f;
            #pragma unroll 8
            for (int d = 0; d < DD; d++) s += w[d] * a[d];
            g_ve[l][k] = s;
        }
        return;
    }
    int idx = blockIdx.x * blockDim.x + threadIdx.x;   // 3*128*128
    int l = idx >> 14;
    int rem = idx & 16383;
    int k = rem >> 7, n = rem & 127;
    float v = Ws[idx];
    __nv_bfloat16 h = __float2bfloat16_rn(v);
    float lo = v - __bfloat162float(h);
    g_wh[l][n * DD + k] = h;
    g_wl[l][n * DD + k] = __float2bfloat16_rn(lo);
}

__global__ void k_hist(const int* __restrict__ ei) {
    int e = blockIdx.x * blockDim.x + threadIdx.x;
    if (e < NE) atomicAdd(&g_cnt[ei[NE + e]], 1);
}

__global__ void k_bsum() {
    int b = blockIdx.x, t = threadIdx.x;
    int v = g_cnt[b * 256 + t] + 1;
    #pragma unroll
    for (int o = 16; o; o >>= 1) v += __shfl_xor_sync(0xffffffffu, v, o);
    __shared__ int ws[8];
    if ((t & 31) == 0) ws[t >> 5] = v;
    __syncthreads();
    if (t < 8) {
        int s = ws[t];
        #pragma unroll
        for (int o = 4; o; o >>= 1) s += __shfl_xor_sync(0xffu, s, o);
        if (t == 0) g_bsum[b] = s;
    }
}

__global__ void k_bscan() {
    int t = threadIdx.x;
    int lane = t & 31, w = t >> 5;
    int v = g_bsum[t];
    int x = v;
    #pragma unroll
    for (int o = 1; o < 32; o <<= 1) {
        int y = __shfl_up_sync(0xffffffffu, x, o);
        if (lane >= o) x += y;
    }
    __shared__ int ws[8];
    if (lane == 31) ws[w] = x;
    __syncthreads();
    if (t < 8) {
        int s = ws[t];
        #pragma unroll
        for (int o = 1; o < 8; o <<= 1) {
            int y = __shfl_up_sync(0xffu, s, o);
            if (t >= o) s += y;
        }
        ws[t] = s;
    }
    __syncthreads();
    int incl = x + (w ? ws[w - 1] : 0);
    g_bsum[t] = incl - v;
    if (t == 255) g_rowptr[NN] = EX;
}

__global__ void k_rowptr() {
    int b = blockIdx.x, t = threadIdx.x;
    int n = b * 256 + t;
    int lane = t & 31, w = t >> 5;
    int v = g_cnt[n] + 1;
    int x = v;
    #pragma unroll
    for (int o = 1; o < 32; o <<= 1) {
        int y = __shfl_up_sync(0xffffffffu, x, o);
        if (lane >= o) x += y;
    }
    __shared__ int ws[8];
    if (lane == 31) ws[w] = x;
    __syncthreads();
    if (t < 8) {
        int s = ws[t];
        #pragma unroll
        for (int o = 1; o < 8; o <<= 1) {
            int y = __shfl_up_sync(0xffu, s, o);
            if (t >= o) s += y;
        }
        ws[t] = s;
    }
    __syncthreads();
    int excl = x - v + (w ? ws[w - 1] : 0) + g_bsum[b];
    g_rowptr[n] = excl;
    g_wslot[n] = excl;
}

__global__ void k_scatter(const int* __restrict__ ei, const float* __restrict__ ea) {
    __shared__ float sve[96];
    if (threadIdx.x < 96) sve[threadIdx.x] = ((const float*)g_ve)[threadIdx.x];
    __syncthreads();
    int e = blockIdx.x * blockDim.x + threadIdx.x;
    if (e >= NE) return;
    int s = ei[e];
    int d = ei[NE + e];
    const float4* a4 = (const float4*)(ea + (size_t)e * 32);
    float dot0 = 0.f, dot1 = 0.f, dot2 = 0.f;
    #pragma unroll
    for (int q = 0; q < 8; q++) {
        float4 v = a4[q];
        const float* v0 = sve + 0 * 32 + q * 4;
        const float* v1 = sve + 1 * 32 + q * 4;
        const float* v2 = sve + 2 * 32 + q * 4;
        dot0 += v.x * v0[0] + v.y * v0[1] + v.z * v0[2] + v.w * v0[3];
        dot1 += v.x * v1[0] + v.y * v1[1] + v.z * v1[2] + v.w * v1[3];
        dot2 += v.x * v2[0] + v.y * v2[1] + v.z * v2[2] + v.w * v2[3];
    }
    int p = atomicAdd(&g_wslot[d], 1);
    g_srcs[p] = s;
    g_ess[0][p] = dot0; g_ess[1][p] = dot1; g_ess[2][p] = dot2;
    atomicAdd(&g_essum[0][d], dot0);
    atomicAdd(&g_essum[1][d], dot1);
    atomicAdd(&g_essum[2][d], dot2);
}

__global__ void k_selfloop() {
    int n = blockIdx.x * blockDim.x + threadIdx.x;
    if (n >= NN) return;
    int pos = g_rowptr[n + 1] - 1;
    g_srcs[pos] = n;
    float cf = fmaxf((float)g_cnt[n], 1.0f);
    g_ess[0][pos] = g_essum[0][n] / cf;
    g_ess[1][pos] = g_essum[1][n] / cf;
    g_ess[2][pos] = g_essum[2][n] / cf;
}

// ---------------- tensor-core GEMM + fused rowdots ----------------
__device__ __forceinline__ void mma16816(float* c, const unsigned* a, const unsigned* b) {
    asm volatile(
        "mma.sync.aligned.m16n8k16.row.col.f32.bf16.bf16.f32 "
        "{%0,%1,%2,%3},{%4,%5,%6,%7},{%8,%9},{%0,%1,%2,%3};\n"
        : "+f"(c[0]), "+f"(c[1]), "+f"(c[2]), "+f"(c[3])
        : "r"(a[0]), "r"(a[1]), "r"(a[2]), "r"(a[3]), "r"(b[0]), "r"(b[1]));
}

__device__ __forceinline__ void ldm_x4(unsigned* r, unsigned addr) {
    asm volatile("ldmatrix.sync.aligned.m8n8.x4.shared.b16 {%0,%1,%2,%3},[%4];"
                 : "=r"(r[0]), "=r"(r[1]), "=r"(r[2]), "=r"(r[3]) : "r"(addr));
}

__device__ __forceinline__ void ldm_x2(unsigned* r, unsigned addr) {
    asm volatile("ldmatrix.sync.aligned.m8n8.x2.shared.b16 {%0,%1},[%2];"
                 : "=r"(r[0]), "=r"(r[1]) : "r"(addr));
}

extern __shared__ char smem_raw[];

__global__ void __launch_bounds__(256) k_gemm_tc(const float* __restrict__ Ain, int l,
                                                 const float* __restrict__ a_s,
                                                 const float* __restrict__ a_d) {
    const float* A = Ain ? Ain : g_x;
    __nv_bfloat16* sAh = (__nv_bfloat16*)smem_raw;      // [128][PK]
    __nv_bfloat16* sAl = sAh + 128 * PK;
    __nv_bfloat16* sBh = sAl + 128 * PK;                // n-major [128][PK]
    __nv_bfloat16* sBl = sBh + 128 * PK;

    int tid = threadIdx.x;
    int row0 = blockIdx.x * 128;

    // stage A: fp32 -> bf16 hi/lo split, conflict-free 8B stores
    {
        const float4* A4 = (const float4*)(A + (size_t)row0 * DD);
        #pragma unroll
        for (int it = 0; it < 16; it++) {
            int idx = it * 256 + tid;
            int r = idx >> 5;
            int c = (idx & 31) << 2;
            float4 v = A4[idx];
            __nv_bfloat16 h0 = __float2bfloat16_rn(v.x), h1 = __float2bfloat16_rn(v.y);
            __nv_bfloat16 h2 = __float2bfloat16_rn(v.z), h3 = __float2bfloat16_rn(v.w);
            __nv_bfloat162 ha, hb, la, lb;
            ha.x = h0; ha.y = h1; hb.x = h2; hb.y = h3;
            la = __floats2bfloat162_rn(v.x - __bfloat162float(h0), v.y - __bfloat162float(h1));
            lb = __floats2bfloat162_rn(v.z - __bfloat162float(h2), v.w - __bfloat162float(h3));
            unsigned* dh = (unsigned*)(sAh + r * PK + c);
            unsigned* dl = (unsigned*)(sAl + r * PK + c);
            dh[0] = *(unsigned*)&ha; dh[1] = *(unsigned*)&hb;
            dl[0] = *(unsigned*)&la; dl[1] = *(unsigned*)&lb;
        }
    }
    // stage W (pre-split, n-major): pure uint4 copy, conflict-free
    {
        const uint4* wh4 = (const uint4*)g_wh[l];
        const uint4* wl4 = (const uint4*)g_wl[l];
        #pragma unroll
        for (int it = 0; it < 8; it++) {
            int idx = it * 256 + tid;
            int n = idx >> 4;
            int kc = idx & 15;
            ((uint4*)(sBh + n * PK))[kc] = wh4[idx];
            ((uint4*)(sBl + n * PK))[kc] = wl4[idx];
        }
    }
    __syncthreads();

    int wid = tid >> 5, lane = tid & 31;
    int g = lane >> 2, tq = lane & 3;
    int wm = wid >> 2, wn = wid & 3;        // 2 x 4 warp grid: 64x32 per warp
    int mbase = wm * 64, nbase = wn * 32;

    unsigned baseAh, baseAl, baseBh, baseBl;
    {
        int aoff = ((mbase + (lane & 15)) * PK + ((lane >> 4) << 3)) * 2;
        baseAh = (unsigned)__cvta_generic_to_shared(sAh) + aoff;
        baseAl = (unsigned)__cvta_generic_to_shared(sAl) + aoff;
        int boff = ((nbase + (lane & 7)) * PK + (((lane >> 3) & 1) << 3)) * 2;
        baseBh = (unsigned)__cvta_generic_to_shared(sBh) + boff;
        baseBl = (unsigned)__cvta_generic_to_shared(sBl) + boff;
    }

    float acc[4][4][4];
    #pragma unroll
    for (int i = 0; i < 4; i++)
        #pragma unroll
        for (int j = 0; j < 4; j++)
            #pragma unroll
            for (int q = 0; q < 4; q++) acc[i][j][q] = 0.f;

    #pragma unroll
    for (int kk = 0; kk < 8; kk++) {
        unsigned kb = kk * 32;
        unsigned Ah[4][4], Al[4][4], Bh[4][2], Bl[4][2];
        #pragma unroll
        for (int i = 0; i < 4; i++) {
            unsigned off = (unsigned)(i * 16 * PK * 2) + kb;
            ldm_x4(Ah[i], baseAh + off);
            ldm_x4(Al[i], baseAl + off);
        }
        #pragma unroll
        for (int j = 0; j < 4; j++) {
            unsigned off = (unsigned)(j * 8 * PK * 2) + kb;
            ldm_x2(Bh[j], baseBh + off);
            ldm_x2(Bl[j], baseBl + off);
        }
        #pragma unroll
        for (int i = 0; i < 4; i++)
            #pragma unroll
            for (int j = 0; j < 4; j++) {
                mma16816(acc[i][j], Ah[i], Bh[j]);
                mma16816(acc[i][j], Al[i], Bh[j]);
                mma16816(acc[i][j], Ah[i], Bl[j]);
            }
    }

    // store h
    #pragma unroll
    for (int i = 0; i < 4; i++) {
        int r = row0 + mbase + i * 16 + g;
        #pragma unroll
        for (int j = 0; j < 4; j++) {
            int c = nbase + j * 8 + 2 * tq;
            *(float2*)(g_h + (size_t)r * DD + c) = make_float2(acc[i][j][0], acc[i][j][1]);
            *(float2*)(g_h + (size_t)(r + 8) * DD + c) = make_float2(acc[i][j][2], acc[i][j][3]);
        }
    }

    // fused rowdots: as[r] = h_r . att_src, ad[r] = h_r . att_dst
    // per-thread partials over its 8 columns, shfl-reduce across tq, smem-reduce across wn.
    float asv[4][2], adv[4][2];   // att values at this thread's 8 columns
    #pragma unroll
    for (int j = 0; j < 4; j++) {
        int c = nbase + j * 8 + 2 * tq;
        asv[j][0] = a_s[c]; asv[j][1] = a_s[c + 1];
        adv[j][0] = a_d[c]; adv[j][1] = a_d[c + 1];
    }
    __syncthreads();                      // mainloop smem reads done; safe to alias
    float* s_red = (float*)smem_raw;      // [128] src sums, [128] dst sums
    if (tid < 128) { s_red[tid] = 0.f; s_red[128 + tid] = 0.f; }
    __syncthreads();
    #pragma unroll
    for (int i = 0; i < 4; i++) {
        float ps0 = 0.f, pd0 = 0.f, ps1 = 0.f, pd1 = 0.f;
        #pragma unroll
        for (int j = 0; j < 4; j++) {
            ps0 += acc[i][j][0] * asv[j][0] + acc[i][j][1] * asv[j][1];
            pd0 += acc[i][j][0] * adv[j][0] + acc[i][j][1] * adv[j][1];
            ps1 += acc[i][j][2] * asv[j][0] + acc[i][j][3] * asv[j][1];
            pd1 += acc[i][j][2] * adv[j][0] + acc[i][j][3] * adv[j][1];
        }
        #pragma unroll
        for (int o = 1; o < 4; o <<= 1) {
            ps0 += __shfl_xor_sync(0xffffffffu, ps0, o);
            pd0 += __shfl_xor_sync(0xffffffffu, pd0, o);
            ps1 += __shfl_xor_sync(0xffffffffu, ps1, o);
            pd1 += __shfl_xor_sync(0xffffffffu, pd1, o);
        }
        if (tq == 0) {
            int rl = mbase + i * 16 + g;
            atomicAdd(&s_red[rl], ps0);
            atomicAdd(&s_red[128 + rl], pd0);
            atomicAdd(&s_red[rl + 8], ps1);
            atomicAdd(&s_red[128 + rl + 8], pd1);
        }
    }
    __syncthreads();
    if (tid < 128) {
        g_as[row0 + tid] = s_red[tid];
        g_ad[row0 + tid] = s_red[128 + tid];
    }
}

// ---------------- fused attention + aggregate + bias + GELU ----------------
__global__ void __launch_bounds__(256) k_agg(int l, const float* __restrict__ bias_l,
                                             float* __restrict__ outp) {
    int d = (blockIdx.x * blockDim.x + threadIdx.x) >> 5;
    int lane = threadIdx.x & 31;
    if (d >= NN) return;
    float* out = outp ? outp : g_x;

    int beg = g_rowptr[d];
    int end = g_rowptr[d + 1];
    float add = g_ad[d];
    const float* ess = g_ess[l];

    float m = -3.0e38f;
    for (int j = beg + lane; j < end; j += 32) {
        int s = g_srcs[j];
        float al = g_as[s] + add + ess[j];
        al = al > 0.f ? al : 0.2f * al;
        m = fmaxf(m, al);
    }
    #pragma unroll
    for (int o = 16; o; o >>= 1) m = fmaxf(m, __shfl_xor_sync(0xffffffffu, m, o));

    float den = 0.f;
    float4 acc = make_float4(0.f, 0.f, 0.f, 0.f);
    const float4* h4 = (const float4*)g_h;

    for (int base = beg; base < end; base += 32) {
        int j = base + lane;
        float ex = 0.f;
        int s = 0;
        if (j < end) {
            s = g_srcs[j];
            float al = g_as[s] + add + ess[j];
            al = al > 0.f ? al : 0.2f * al;
            ex = __expf(al - m);
        }
        den += ex;
        int cnt = end - base;
        if (cnt > 32) cnt = 32;
        for (int t = 0; t < cnt; t++) {
            float ext = __shfl_sync(0xffffffffu, ex, t);
            int st = __shfl_sync(0xffffffffu, s, t);
            float4 v = h4[(size_t)st * 32 + lane];
            acc.x = fmaf(ext, v.x, acc.x);
            acc.y = fmaf(ext, v.y, acc.y);
            acc.z = fmaf(ext, v.z, acc.z);
            acc.w = fmaf(ext, v.w, acc.w);
        }
    }
    #pragma unroll
    for (int o = 16; o; o >>= 1) den += __shfl_xor_sync(0xffffffffu, den, o);
    float r = 1.0f / den;

    float4 b4 = ((const float4*)bias_l)[lane];
    float4 o4;
    o4.x = gelu_f(fmaf(acc.x, r, b4.x));
    o4.y = gelu_f(fmaf(acc.y, r, b4.y));
    o4.z = gelu_f(fmaf(acc.z, r, b4.z));
    o4.w = gelu_f(fmaf(acc.w, r, b4.w));
    ((float4*)out)[(size_t)d * 32 + lane] = o4;
}

// ---------------- launch ----------------
extern "C" void kernel_launch(void* const* d_in, const int* in_sizes, int n_in,
                              void* d_out, int out_size) {
    const float* x    = (const float*)d_in[0];
    const int*   ei   = (const int*)d_in[1];
    const float* ea   = (const float*)d_in[2];
    const float* Ws   = (const float*)d_in[3];
    const float* a_s  = (const float*)d_in[4];
    const float* a_d  = (const float*)d_in[5];
    const float* We   = (const float*)d_in[6];
    const float* ae   = (const float*)d_in[7];
    const float* bias = (const float*)d_in[8];
    float* out = (float*)d_out;

    const int SMEM_SZ = 4 * 128 * PK * 2;  // 139264 B
    cudaFuncSetAttribute(k_gemm_tc, cudaFuncAttributeMaxDynamicSharedMemorySize, SMEM_SZ);

    k_init<<<NN / 256, 256>>>();
    k_wsplit<<<193, 256>>>(Ws, We, ae);
    k_hist<<<NE / 256, 256>>>(ei);
    k_bsum<<<256, 256>>>();
    k_bscan<<<1, 256>>>();
    k_rowptr<<<256, 256>>>();
    k_scatter<<<NE / 256, 256>>>(ei, ea);
    k_selfloop<<<NN / 256, 256>>>();

    for (int l = 0; l < 3; l++) {
        const float* xin = (l == 0) ? x : nullptr;
        k_gemm_tc<<<NN / 128, 256, SMEM_SZ>>>(xin, l, a_s + l * DD, a_d + l * DD);
        float* outl = (l == 2) ? out : nullptr;
        k_agg<<<NN / 8, 256>>>(l, bias + l * DD, outl);
    }
}

// round 6
// speedup vs baseline: 2.2312x; 1.0464x over previous
#include <cuda_runtime.h>
#include <cuda_bf16.h>
#include <cuda_fp16.h>
#include <math.h>

#define NN 65536
#define NE 524288
#define EX (NE + NN)
#define DD 128
#define PK 136   // padded k-dim (bf16 elems); 272B rows => ldmatrix conflict-free

// ---------------- scratch (device globals: allocation-free) ----------------
__device__ __half g_hh[(size_t)NN * DD];    // 16MB: h in fp16 (agg gather path)
__device__ float g_x[(size_t)NN * DD];      // 32MB: layer activations
__device__ float g_as[NN];
__device__ float g_ad[NN];
__device__ float g_ess[3][EX];
__device__ float g_essum[3][NN];
__device__ int   g_srcs[EX];
__device__ int   g_rowptr[NN + 1];
__device__ int   g_wslot[NN];
__device__ int   g_cnt[NN];
__device__ int   g_bsum[256];
__device__ float g_ve[3][32];
__device__ __nv_bfloat16 g_wh[3][DD * DD];   // W^T split hi (n-major)
__device__ __nv_bfloat16 g_wl[3][DD * DD];   // W^T split lo (n-major)

__device__ __forceinline__ float gelu_f(float x) {
    return 0.5f * x * (1.0f + erff(x * 0.7071067811865476f));
}

// ---------------- preprocessing ----------------
// blocks 0..191: split W -> bf16 hi/lo (transposed, n-major)
// block 192:     ve[l] = We[l] @ att_edge[l]
// blocks 193..448: zero cnt/essum
__global__ void k_wsplit(const float* __restrict__ Ws,
                         const float* __restrict__ We, const float* __restrict__ ae) {
    int b = blockIdx.x;
    if (b >= 193) {
        int i = (b - 193) * 256 + threadIdx.x;
        if (i < NN) {
            g_cnt[i] = 0;
            g_essum[0][i] = 0.f; g_essum[1][i] = 0.f; g_essum[2][i] = 0.f;
        }
        return;
    }
    if (b == 192) {
        int t = threadIdx.x;
        if (t < 96) {
            int l = t / 32, k = t % 32;
            const float* w = We + l * 32 * DD + k * DD;
            const float* a = ae + l * DD;
            float s = 0.f;
            #pragma unroll 8
            for (int d = 0; d < DD; d++) s += w[d] * a[d];
            g_ve[l][k] = s;
        }
        return;
    }
    int idx = b * blockDim.x + threadIdx.x;   // 3*128*128
    int l = idx >> 14;
    int rem = idx & 16383;
    int k = rem >> 7, n = rem & 127;
    float v = Ws[idx];
    __nv_bfloat16 h = __float2bfloat16_rn(v);
    float lo = v - __bfloat162float(h);
    g_wh[l][n * DD + k] = h;
    g_wl[l][n * DD + k] = __float2bfloat16_rn(lo);
}

__global__ void k_hist(const int* __restrict__ ei) {
    int e = blockIdx.x * blockDim.x + threadIdx.x;
    if (e < NE) atomicAdd(&g_cnt[ei[NE + e]], 1);
}

__global__ void k_bsum() {
    int b = blockIdx.x, t = threadIdx.x;
    int v = g_cnt[b * 256 + t] + 1;
    #pragma unroll
    for (int o = 16; o; o >>= 1) v += __shfl_xor_sync(0xffffffffu, v, o);
    __shared__ int ws[8];
    if ((t & 31) == 0) ws[t >> 5] = v;
    __syncthreads();
    if (t < 8) {
        int s = ws[t];
        #pragma unroll
        for (int o = 4; o; o >>= 1) s += __shfl_xor_sync(0xffu, s, o);
        if (t == 0) g_bsum[b] = s;
    }
}

__global__ void k_bscan() {
    int t = threadIdx.x;
    int lane = t & 31, w = t >> 5;
    int v = g_bsum[t];
    int x = v;
    #pragma unroll
    for (int o = 1; o < 32; o <<= 1) {
        int y = __shfl_up_sync(0xffffffffu, x, o);
        if (lane >= o) x += y;
    }
    __shared__ int ws[8];
    if (lane == 31) ws[w] = x;
    __syncthreads();
    if (t < 8) {
        int s = ws[t];
        #pragma unroll
        for (int o = 1; o < 8; o <<= 1) {
            int y = __shfl_up_sync(0xffu, s, o);
            if (t >= o) s += y;
        }
        ws[t] = s;
    }
    __syncthreads();
    int incl = x + (w ? ws[w - 1] : 0);
    g_bsum[t] = incl - v;
    if (t == 255) g_rowptr[NN] = EX;
}

__global__ void k_rowptr() {
    int b = blockIdx.x, t = threadIdx.x;
    int n = b * 256 + t;
    int lane = t & 31, w = t >> 5;
    int v = g_cnt[n] + 1;
    int x = v;
    #pragma unroll
    for (int o = 1; o < 32; o <<= 1) {
        int y = __shfl_up_sync(0xffffffffu, x, o);
        if (lane >= o) x += y;
    }
    __shared__ int ws[8];
    if (lane == 31) ws[w] = x;
    __syncthreads();
    if (t < 8) {
        int s = ws[t];
        #pragma unroll
        for (int o = 1; o < 8; o <<= 1) {
            int y = __shfl_up_sync(0xffu, s, o);
            if (t >= o) s += y;
        }
        ws[t] = s;
    }
    __syncthreads();
    int excl = x - v + (w ? ws[w - 1] : 0) + g_bsum[b];
    g_rowptr[n] = excl;
    g_wslot[n] = excl;
}

__global__ void k_scatter(const int* __restrict__ ei, const float* __restrict__ ea) {
    __shared__ float sve[96];
    if (threadIdx.x < 96) sve[threadIdx.x] = ((const float*)g_ve)[threadIdx.x];
    __syncthreads();
    int e = blockIdx.x * blockDim.x + threadIdx.x;
    if (e >= NE) return;
    int s = ei[e];
    int d = ei[NE + e];
    const float4* a4 = (const float4*)(ea + (size_t)e * 32);
    float dot0 = 0.f, dot1 = 0.f, dot2 = 0.f;
    #pragma unroll
    for (int q = 0; q < 8; q++) {
        float4 v = a4[q];
        const float* v0 = sve + 0 * 32 + q * 4;
        const float* v1 = sve + 1 * 32 + q * 4;
        const float* v2 = sve + 2 * 32 + q * 4;
        dot0 += v.x * v0[0] + v.y * v0[1] + v.z * v0[2] + v.w * v0[3];
        dot1 += v.x * v1[0] + v.y * v1[1] + v.z * v1[2] + v.w * v1[3];
        dot2 += v.x * v2[0] + v.y * v2[1] + v.z * v2[2] + v.w * v2[3];
    }
    int p = atomicAdd(&g_wslot[d], 1);
    g_srcs[p] = s;
    g_ess[0][p] = dot0; g_ess[1][p] = dot1; g_ess[2][p] = dot2;
    atomicAdd(&g_essum[0][d], dot0);
    atomicAdd(&g_essum[1][d], dot1);
    atomicAdd(&g_essum[2][d], dot2);
}

__global__ void k_selfloop() {
    int n = blockIdx.x * blockDim.x + threadIdx.x;
    if (n >= NN) return;
    int pos = g_rowptr[n + 1] - 1;
    g_srcs[pos] = n;
    float cf = fmaxf((float)g_cnt[n], 1.0f);
    g_ess[0][pos] = g_essum[0][n] / cf;
    g_ess[1][pos] = g_essum[1][n] / cf;
    g_ess[2][pos] = g_essum[2][n] / cf;
}

// ---------------- tensor-core GEMM + fused rowdots, fp16 h output ----------------
__device__ __forceinline__ void mma16816(float* c, const unsigned* a, const unsigned* b) {
    asm volatile(
        "mma.sync.aligned.m16n8k16.row.col.f32.bf16.bf16.f32 "
        "{%0,%1,%2,%3},{%4,%5,%6,%7},{%8,%9},{%0,%1,%2,%3};\n"
        : "+f"(c[0]), "+f"(c[1]), "+f"(c[2]), "+f"(c[3])
        : "r"(a[0]), "r"(a[1]), "r"(a[2]), "r"(a[3]), "r"(b[0]), "r"(b[1]));
}

__device__ __forceinline__ void ldm_x4(unsigned* r, unsigned addr) {
    asm volatile("ldmatrix.sync.aligned.m8n8.x4.shared.b16 {%0,%1,%2,%3},[%4];"
                 : "=r"(r[0]), "=r"(r[1]), "=r"(r[2]), "=r"(r[3]) : "r"(addr));
}

__device__ __forceinline__ void ldm_x2(unsigned* r, unsigned addr) {
    asm volatile("ldmatrix.sync.aligned.m8n8.x2.shared.b16 {%0,%1},[%2];"
                 : "=r"(r[0]), "=r"(r[1]) : "r"(addr));
}

extern __shared__ char smem_raw[];

__global__ void __launch_bounds__(256) k_gemm_tc(const float* __restrict__ Ain, int l,
                                                 const float* __restrict__ a_s,
                                                 const float* __restrict__ a_d) {
    const float* A = Ain ? Ain : g_x;
    __nv_bfloat16* sAh = (__nv_bfloat16*)smem_raw;      // [128][PK]
    __nv_bfloat16* sAl = sAh + 128 * PK;
    __nv_bfloat16* sBh = sAl + 128 * PK;                // n-major [128][PK]
    __nv_bfloat16* sBl = sBh + 128 * PK;

    int tid = threadIdx.x;
    int row0 = blockIdx.x * 128;

    {
        const float4* A4 = (const float4*)(A + (size_t)row0 * DD);
        #pragma unroll
        for (int it = 0; it < 16; it++) {
            int idx = it * 256 + tid;
            int r = idx >> 5;
            int c = (idx & 31) << 2;
            float4 v = A4[idx];
            __nv_bfloat16 h0 = __float2bfloat16_rn(v.x), h1 = __float2bfloat16_rn(v.y);
            __nv_bfloat16 h2 = __float2bfloat16_rn(v.z), h3 = __float2bfloat16_rn(v.w);
            __nv_bfloat162 ha, hb, la, lb;
            ha.x = h0; ha.y = h1; hb.x = h2; hb.y = h3;
            la = __floats2bfloat162_rn(v.x - __bfloat162float(h0), v.y - __bfloat162float(h1));
            lb = __floats2bfloat162_rn(v.z - __bfloat162float(h2), v.w - __bfloat162float(h3));
            unsigned* dh = (unsigned*)(sAh + r * PK + c);
            unsigned* dl = (unsigned*)(sAl + r * PK + c);
            dh[0] = *(unsigned*)&ha; dh[1] = *(unsigned*)&hb;
            dl[0] = *(unsigned*)&la; dl[1] = *(unsigned*)&lb;
        }
    }
    {
        const uint4* wh4 = (const uint4*)g_wh[l];
        const uint4* wl4 = (const uint4*)g_wl[l];
        #pragma unroll
        for (int it = 0; it < 8; it++) {
            int idx = it * 256 + tid;
            int n = idx >> 4;
            int kc = idx & 15;
            ((uint4*)(sBh + n * PK))[kc] = wh4[idx];
            ((uint4*)(sBl + n * PK))[kc] = wl4[idx];
        }
    }
    __syncthreads();

    int wid = tid >> 5, lane = tid & 31;
    int g = lane >> 2, tq = lane & 3;
    int wm = wid >> 2, wn = wid & 3;
    int mbase = wm * 64, nbase = wn * 32;

    unsigned baseAh, baseAl, baseBh, baseBl;
    {
        int aoff = ((mbase + (lane & 15)) * PK + ((lane >> 4) << 3)) * 2;
        baseAh = (unsigned)__cvta_generic_to_shared(sAh) + aoff;
        baseAl = (unsigned)__cvta_generic_to_shared(sAl) + aoff;
        int boff = ((nbase + (lane & 7)) * PK + (((lane >> 3) & 1) << 3)) * 2;
        baseBh = (unsigned)__cvta_generic_to_shared(sBh) + boff;
        baseBl = (unsigned)__cvta_generic_to_shared(sBl) + boff;
    }

    float acc[4][4][4];
    #pragma unroll
    for (int i = 0; i < 4; i++)
        #pragma unroll
        for (int j = 0; j < 4; j++)
            #pragma unroll
            for (int q = 0; q < 4; q++) acc[i][j][q] = 0.f;

    #pragma unroll
    for (int kk = 0; kk < 8; kk++) {
        unsigned kb = kk * 32;
        unsigned Ah[4][4], Al[4][4], Bh[4][2], Bl[4][2];
        #pragma unroll
        for (int i = 0; i < 4; i++) {
            unsigned off = (unsigned)(i * 16 * PK * 2) + kb;
            ldm_x4(Ah[i], baseAh + off);
            ldm_x4(Al[i], baseAl + off);
        }
        #pragma unroll
        for (int j = 0; j < 4; j++) {
            unsigned off = (unsigned)(j * 8 * PK * 2) + kb;
            ldm_x2(Bh[j], baseBh + off);
            ldm_x2(Bl[j], baseBl + off);
        }
        #pragma unroll
        for (int i = 0; i < 4; i++)
            #pragma unroll
            for (int j = 0; j < 4; j++) {
                mma16816(acc[i][j], Ah[i], Bh[j]);
                mma16816(acc[i][j], Al[i], Bh[j]);
                mma16816(acc[i][j], Ah[i], Bl[j]);
            }
    }

    // store h as fp16
    #pragma unroll
    for (int i = 0; i < 4; i++) {
        int r = row0 + mbase + i * 16 + g;
        #pragma unroll
        for (int j = 0; j < 4; j++) {
            int c = nbase + j * 8 + 2 * tq;
            *(__half2*)(g_hh + (size_t)r * DD + c) =
                __float22half2_rn(make_float2(acc[i][j][0], acc[i][j][1]));
            *(__half2*)(g_hh + (size_t)(r + 8) * DD + c) =
                __float22half2_rn(make_float2(acc[i][j][2], acc[i][j][3]));
        }
    }

    // fused rowdots
    float asv[4][2], adv[4][2];
    #pragma unroll
    for (int j = 0; j < 4; j++) {
        int c = nbase + j * 8 + 2 * tq;
        asv[j][0] = a_s[c]; asv[j][1] = a_s[c + 1];
        adv[j][0] = a_d[c]; adv[j][1] = a_d[c + 1];
    }
    __syncthreads();
    float* s_red = (float*)smem_raw;
    if (tid < 128) { s_red[tid] = 0.f; s_red[128 + tid] = 0.f; }
    __syncthreads();
    #pragma unroll
    for (int i = 0; i < 4; i++) {
        float ps0 = 0.f, pd0 = 0.f, ps1 = 0.f, pd1 = 0.f;
        #pragma unroll
        for (int j = 0; j < 4; j++) {
            ps0 += acc[i][j][0] * asv[j][0] + acc[i][j][1] * asv[j][1];
            pd0 += acc[i][j][0] * adv[j][0] + acc[i][j][1] * adv[j][1];
            ps1 += acc[i][j][2] * asv[j][0] + acc[i][j][3] * asv[j][1];
            pd1 += acc[i][j][2] * adv[j][0] + acc[i][j][3] * adv[j][1];
        }
        #pragma unroll
        for (int o = 1; o < 4; o <<= 1) {
            ps0 += __shfl_xor_sync(0xffffffffu, ps0, o);
            pd0 += __shfl_xor_sync(0xffffffffu, pd0, o);
            ps1 += __shfl_xor_sync(0xffffffffu, ps1, o);
            pd1 += __shfl_xor_sync(0xffffffffu, pd1, o);
        }
        if (tq == 0) {
            int rl = mbase + i * 16 + g;
            atomicAdd(&s_red[rl], ps0);
            atomicAdd(&s_red[128 + rl], pd0);
            atomicAdd(&s_red[rl + 8], ps1);
            atomicAdd(&s_red[128 + rl + 8], pd1);
        }
    }
    __syncthreads();
    if (tid < 128) {
        g_as[row0 + tid] = s_red[tid];
        g_ad[row0 + tid] = s_red[128 + tid];
    }
}

// ---------------- single-pass online-softmax aggregate + bias + GELU ----------------
__global__ void __launch_bounds__(256) k_agg(int l, const float* __restrict__ bias_l,
                                             float* __restrict__ outp) {
    int d = (blockIdx.x * blockDim.x + threadIdx.x) >> 5;
    int lane = threadIdx.x & 31;
    if (d >= NN) return;
    float* out = outp ? outp : g_x;

    int beg = g_rowptr[d];
    int end = g_rowptr[d + 1];
    float add = g_ad[d];
    const float* ess = g_ess[l];
    const uint2* h2 = (const uint2*)g_hh;   // 4 halves per lane

    float m = -3.0e38f;
    float den = 0.f;
    float4 acc = make_float4(0.f, 0.f, 0.f, 0.f);

    for (int base = beg; base < end; base += 32) {
        int j = base + lane;
        float al = -3.0e38f;
        int s = 0;
        if (j < end) {
            s = g_srcs[j];
            al = g_as[s] + add + ess[j];
            al = al > 0.f ? al : 0.2f * al;
        }
        // chunk max
        float cm = al;
        #pragma unroll
        for (int o = 16; o; o >>= 1) cm = fmaxf(cm, __shfl_xor_sync(0xffffffffu, cm, o));
        float m2 = fmaxf(m, cm);
        float scale = __expf(m - m2);
        den *= scale;
        acc.x *= scale; acc.y *= scale; acc.z *= scale; acc.w *= scale;
        m = m2;

        float ex = (j < end) ? __expf(al - m2) : 0.f;
        den += ex;

        int cnt = end - base;
        if (cnt > 32) cnt = 32;
        for (int t = 0; t < cnt; t++) {
            float ext = __shfl_sync(0xffffffffu, ex, t);
            int st = __shfl_sync(0xffffffffu, s, t);
            uint2 raw = h2[(size_t)st * 32 + lane];
            float2 v0 = __half22float2(*(__half2*)&raw.x);
            float2 v1 = __half22float2(*(__half2*)&raw.y);
            acc.x = fmaf(ext, v0.x, acc.x);
            acc.y = fmaf(ext, v0.y, acc.y);
            acc.z = fmaf(ext, v1.x, acc.z);
            acc.w = fmaf(ext, v1.y, acc.w);
        }
    }
    #pragma unroll
    for (int o = 16; o; o >>= 1) den += __shfl_xor_sync(0xffffffffu, den, o);
    float r = 1.0f / den;

    float4 b4 = ((const float4*)bias_l)[lane];
    float4 o4;
    o4.x = gelu_f(fmaf(acc.x, r, b4.x));
    o4.y = gelu_f(fmaf(acc.y, r, b4.y));
    o4.z = gelu_f(fmaf(acc.z, r, b4.z));
    o4.w = gelu_f(fmaf(acc.w, r, b4.w));
    ((float4*)out)[(size_t)d * 32 + lane] = o4;
}

// ---------------- launch ----------------
extern "C" void kernel_launch(void* const* d_in, const int* in_sizes, int n_in,
                              void* d_out, int out_size) {
    const float* x    = (const float*)d_in[0];
    const int*   ei   = (const int*)d_in[1];
    const float* ea   = (const float*)d_in[2];
    const float* Ws   = (const float*)d_in[3];
    const float* a_s  = (const float*)d_in[4];
    const float* a_d  = (const float*)d_in[5];
    const float* We   = (const float*)d_in[6];
    const float* ae   = (const float*)d_in[7];
    const float* bias = (const float*)d_in[8];
    float* out = (float*)d_out;

    const int SMEM_SZ = 4 * 128 * PK * 2;  // 139264 B
    cudaFuncSetAttribute(k_gemm_tc, cudaFuncAttributeMaxDynamicSharedMemorySize, SMEM_SZ);

    k_wsplit<<<449, 256>>>(Ws, We, ae);
    k_hist<<<NE / 256, 256>>>(ei);
    k_bsum<<<256, 256>>>();
    k_bscan<<<1, 256>>>();
    k_rowptr<<<256, 256>>>();
    k_scatter<<<NE / 256, 256>>>(ei, ea);
    k_selfloop<<<NN / 256, 256>>>();

    for (int l = 0; l < 3; l++) {
        const float* xin = (l == 0) ? x : nullptr;
        k_gemm_tc<<<NN / 128, 256, SMEM_SZ>>>(xin, l, a_s + l * DD, a_d + l * DD);
        float* outl = (l == 2) ? out : nullptr;
        k_agg<<<NN / 8, 256>>>(l, bias + l * DD, outl);
    }
}